// round 1
// baseline (speedup 1.0000x reference)
#include <cuda_runtime.h>
#include <math.h>

#define BB 4
#define SS 4096
#define DD 512

// Scratch (static device globals — allocation-guard safe)
__device__ float g_q[BB * SS * DD];                 //  33.5 MB
__device__ float g_k[BB * SS * DD];                 //  33.5 MB
__device__ float g_v[BB * SS * DD];                 //  33.5 MB
__device__ float g_scores[(size_t)BB * SS * SS];    // 268 MB

// ---------------------------------------------------------------------------
// SGEMM: C[m,n] = sum_k A[m,k] * B'[k,n]
//   BT=1: B row-major [N,K]  (C = A * B^T)   — projections, Q*K^T
//   BT=0: B row-major [K,N]  (C = A * B)     — scores * V
// 128x128 tile, Ktile=8, 256 threads, 8x8 per-thread microtile,
// double-buffered smem with register prefetch.
// All dims assumed multiples of 128 / Ktile (true for this problem).
// ---------------------------------------------------------------------------
template <int BT>
__global__ __launch_bounds__(256, 2)
void sgemm_kernel(const float* __restrict__ Ag, const float* __restrict__ Bg,
                  float* __restrict__ Cg, int M, int N, int K,
                  long long sA, long long sB, long long sC)
{
    const float* A  = Ag + (long long)blockIdx.z * sA;
    const float* Bm = Bg + (long long)blockIdx.z * sB;
    float*       C  = Cg + (long long)blockIdx.z * sC;

    const int lda = K;
    const int ldb = BT ? K : N;
    const int ldc = N;

    __shared__ __align__(16) float As[2][8][132];
    __shared__ __align__(16) float Bs[2][8][132];

    const int tid  = threadIdx.x;
    const int row0 = blockIdx.y * 128;
    const int col0 = blockIdx.x * 128;

    // A tile loader: 128 rows x 8 k, one float4 per thread
    const int aRow = tid >> 1;
    const int aCol = (tid & 1) << 2;
    const float* Aptr = A + (long long)(row0 + aRow) * lda + aCol;

    // B tile loader
    int bRow, bCol;
    const float* Bptr;
    if (BT) {
        bRow = tid >> 1;              // n within tile
        bCol = (tid & 1) << 2;        // k within tile
        Bptr = Bm + (long long)(col0 + bRow) * ldb + bCol;
    } else {
        bRow = tid >> 5;              // k within tile (0..7)
        bCol = (tid & 31) << 2;       // n within tile (0..124)
        Bptr = Bm + (long long)bRow * ldb + col0 + bCol;
    }

    const int ty    = tid >> 4;
    const int tx    = tid & 15;
    const int rBase = ty << 3;
    const int cBase = tx << 3;

    float acc[8][8];
#pragma unroll
    for (int i = 0; i < 8; i++)
#pragma unroll
        for (int j = 0; j < 8; j++) acc[i][j] = 0.0f;

    const int nk = K >> 3;

    // prologue: tile 0 -> buffer 0
    {
        float4 va = *(const float4*)(Aptr);
        float4 vb;
        if (BT) vb = *(const float4*)(Bptr);
        else    vb = *(const float4*)(Bptr);
        As[0][aCol + 0][aRow] = va.x;
        As[0][aCol + 1][aRow] = va.y;
        As[0][aCol + 2][aRow] = va.z;
        As[0][aCol + 3][aRow] = va.w;
        if (BT) {
            Bs[0][bCol + 0][bRow] = vb.x;
            Bs[0][bCol + 1][bRow] = vb.y;
            Bs[0][bCol + 2][bRow] = vb.z;
            Bs[0][bCol + 3][bRow] = vb.w;
        } else {
            *(float4*)&Bs[0][bRow][bCol] = vb;
        }
    }
    __syncthreads();

    for (int kt = 0; kt < nk; kt++) {
        const int buf = kt & 1;

        float4 na, nb;
        const bool more = (kt + 1) < nk;
        if (more) {
            na = *(const float4*)(Aptr + (kt + 1) * 8);
            if (BT) nb = *(const float4*)(Bptr + (kt + 1) * 8);
            else    nb = *(const float4*)(Bptr + (long long)(kt + 1) * 8 * ldb);
        }

#pragma unroll
        for (int kk = 0; kk < 8; kk++) {
            float4 a0 = *(const float4*)&As[buf][kk][rBase];
            float4 a1 = *(const float4*)&As[buf][kk][rBase + 4];
            float4 b0 = *(const float4*)&Bs[buf][kk][cBase];
            float4 b1 = *(const float4*)&Bs[buf][kk][cBase + 4];
            float a[8] = {a0.x, a0.y, a0.z, a0.w, a1.x, a1.y, a1.z, a1.w};
            float b[8] = {b0.x, b0.y, b0.z, b0.w, b1.x, b1.y, b1.z, b1.w};
#pragma unroll
            for (int i = 0; i < 8; i++)
#pragma unroll
                for (int j = 0; j < 8; j++)
                    acc[i][j] = fmaf(a[i], b[j], acc[i][j]);
        }

        if (more) {
            const int nbuf = buf ^ 1;
            As[nbuf][aCol + 0][aRow] = na.x;
            As[nbuf][aCol + 1][aRow] = na.y;
            As[nbuf][aCol + 2][aRow] = na.z;
            As[nbuf][aCol + 3][aRow] = na.w;
            if (BT) {
                Bs[nbuf][bCol + 0][bRow] = nb.x;
                Bs[nbuf][bCol + 1][bRow] = nb.y;
                Bs[nbuf][bCol + 2][bRow] = nb.z;
                Bs[nbuf][bCol + 3][bRow] = nb.w;
            } else {
                *(float4*)&Bs[nbuf][bRow][bCol] = nb;
            }
        }
        __syncthreads();
    }

    // epilogue: 8 rows x 2 float4
#pragma unroll
    for (int i = 0; i < 8; i++) {
        float* cp = C + (long long)(row0 + rBase + i) * ldc + col0 + cBase;
        float4 c0 = make_float4(acc[i][0], acc[i][1], acc[i][2], acc[i][3]);
        float4 c1 = make_float4(acc[i][4], acc[i][5], acc[i][6], acc[i][7]);
        *(float4*)cp       = c0;
        *(float4*)(cp + 4) = c1;
    }
}

// ---------------------------------------------------------------------------
// Row softmax over S=4096 (one block per row), applies 1/sqrt(D) scale first.
// ---------------------------------------------------------------------------
__global__ __launch_bounds__(256)
void softmax_kernel(float* __restrict__ scores)
{
    const float scale = 0.04419417382415922f; // 1/sqrt(512)
    float* p = scores + (long long)blockIdx.x * SS;
    const int tid  = threadIdx.x;
    const int lane = tid & 31;
    const int warp = tid >> 5;

    __shared__ float red_max[8];
    __shared__ float red_sum[8];

    float4 v[4];
    float m = -3.4e38f;
#pragma unroll
    for (int i = 0; i < 4; i++) {
        v[i] = ((float4*)p)[tid + 256 * i];
        v[i].x *= scale; v[i].y *= scale; v[i].z *= scale; v[i].w *= scale;
        m = fmaxf(m, fmaxf(fmaxf(v[i].x, v[i].y), fmaxf(v[i].z, v[i].w)));
    }
#pragma unroll
    for (int off = 16; off > 0; off >>= 1)
        m = fmaxf(m, __shfl_xor_sync(0xffffffffu, m, off));
    if (lane == 0) red_max[warp] = m;
    __syncthreads();
    float gm = red_max[0];
#pragma unroll
    for (int w = 1; w < 8; w++) gm = fmaxf(gm, red_max[w]);

    float s = 0.0f;
#pragma unroll
    for (int i = 0; i < 4; i++) {
        v[i].x = expf(v[i].x - gm);
        v[i].y = expf(v[i].y - gm);
        v[i].z = expf(v[i].z - gm);
        v[i].w = expf(v[i].w - gm);
        s += v[i].x + v[i].y + v[i].z + v[i].w;
    }
#pragma unroll
    for (int off = 16; off > 0; off >>= 1)
        s += __shfl_xor_sync(0xffffffffu, s, off);
    if (lane == 0) red_sum[warp] = s;
    __syncthreads();
    float gs = 0.0f;
#pragma unroll
    for (int w = 0; w < 8; w++) gs += red_sum[w];

    const float inv = 1.0f / gs;
#pragma unroll
    for (int i = 0; i < 4; i++) {
        v[i].x *= inv; v[i].y *= inv; v[i].z *= inv; v[i].w *= inv;
        ((float4*)p)[tid + 256 * i] = v[i];
    }
}

// ---------------------------------------------------------------------------
extern "C" void kernel_launch(void* const* d_in, const int* in_sizes, int n_in,
                              void* d_out, int out_size)
{
    const float* token = (const float*)d_in[0];
    const float* W1    = (const float*)d_in[1];
    const float* W2    = (const float*)d_in[2];
    const float* W3    = (const float*)d_in[3];
    float*       out   = (float*)d_out;

    float *q, *k, *v, *sc;
    cudaGetSymbolAddress((void**)&q,  g_q);
    cudaGetSymbolAddress((void**)&k,  g_k);
    cudaGetSymbolAddress((void**)&v,  g_v);
    cudaGetSymbolAddress((void**)&sc, g_scores);

    const dim3 blk(256);

    // Projections: [16384,512] = token[16384,512] @ W^T  (NT)
    const dim3 gProj(512 / 128, (BB * SS) / 128, 1);   // (4,128,1)
    sgemm_kernel<1><<<gProj, blk>>>(token, W1, q, BB * SS, DD, DD, 0, 0, 0);
    sgemm_kernel<1><<<gProj, blk>>>(token, W2, k, BB * SS, DD, DD, 0, 0, 0);
    sgemm_kernel<1><<<gProj, blk>>>(token, W3, v, BB * SS, DD, DD, 0, 0, 0);

    // Logits: scores[b,s,t] = q[b,s,:] . k[b,t,:]  (NT, batched over z)
    const dim3 gLog(SS / 128, SS / 128, BB);           // (32,32,4)
    sgemm_kernel<1><<<gLog, blk>>>(q, k, sc, SS, SS, DD,
                                   (long long)SS * DD, (long long)SS * DD,
                                   (long long)SS * SS);

    // Softmax rows (scale folded in)
    softmax_kernel<<<BB * SS, 256>>>(sc);

    // Output: out[b,s,:] = scores[b,s,:] @ v[b,:,:]  (NN, batched over z)
    const dim3 gOut(DD / 128, SS / 128, BB);           // (4,32,4)
    sgemm_kernel<0><<<gOut, blk>>>(sc, v, out, SS, DD, SS,
                                   (long long)SS * SS, (long long)SS * DD,
                                   (long long)SS * DD);
}

// round 3
// speedup vs baseline: 3.0060x; 3.0060x over previous
#include <cuda_runtime.h>
#include <cuda_bf16.h>
#include <math.h>
#include <stdint.h>

#define BB 4
#define SS 4096
#define DD 512

// ---------------- scratch (static device globals) ----------------
__device__ __nv_bfloat16 g_thi[BB * SS * DD];
__device__ __nv_bfloat16 g_tlo[BB * SS * DD];
__device__ __nv_bfloat16 g_w1hi[DD * DD];
__device__ __nv_bfloat16 g_w1lo[DD * DD];
__device__ __nv_bfloat16 g_w2hi[DD * DD];
__device__ __nv_bfloat16 g_w2lo[DD * DD];
__device__ __nv_bfloat16 g_w3hi[DD * DD];
__device__ __nv_bfloat16 g_w3lo[DD * DD];
__device__ __nv_bfloat16 g_qhi[BB * SS * DD];
__device__ __nv_bfloat16 g_qlo[BB * SS * DD];
__device__ __nv_bfloat16 g_khi[BB * SS * DD];
__device__ __nv_bfloat16 g_klo[BB * SS * DD];
__device__ __nv_bfloat16 g_vthi[DD * BB * SS];   // V^T [DD, BB*SS]
__device__ __nv_bfloat16 g_vtlo[DD * BB * SS];
__device__ float         g_sc [(size_t)BB * SS * SS];
__device__ __nv_bfloat16 g_phi[(size_t)BB * SS * SS];
__device__ __nv_bfloat16 g_plo[(size_t)BB * SS * SS];

// ---------------- PTX helpers (baseline ISA only: sm_80-class) ----------------
__device__ __forceinline__ uint32_t smem_u32(const void* p) {
    return (uint32_t)__cvta_generic_to_shared(p);
}
__device__ __forceinline__ void cp_async16(uint32_t s, const void* g) {
    asm volatile("cp.async.cg.shared.global [%0], [%1], 16;" :: "r"(s), "l"(g));
}
__device__ __forceinline__ void cp_commit() {
    asm volatile("cp.async.commit_group;" ::: "memory");
}
template <int N>
__device__ __forceinline__ void cp_wait() {
    asm volatile("cp.async.wait_group %0;" :: "n"(N) : "memory");
}
__device__ __forceinline__ void ldsm4(uint32_t* r, uint32_t addr) {
    asm volatile("ldmatrix.sync.aligned.m8n8.x4.shared.b16 {%0,%1,%2,%3}, [%4];"
                 : "=r"(r[0]), "=r"(r[1]), "=r"(r[2]), "=r"(r[3]) : "r"(addr));
}
__device__ __forceinline__ void mma16816(float* d, const uint32_t* a, uint32_t b0, uint32_t b1) {
    asm volatile("mma.sync.aligned.m16n8k16.row.col.f32.bf16.bf16.f32 "
                 "{%0,%1,%2,%3}, {%4,%5,%6,%7}, {%8,%9}, {%0,%1,%2,%3};"
                 : "+f"(d[0]), "+f"(d[1]), "+f"(d[2]), "+f"(d[3])
                 : "r"(a[0]), "r"(a[1]), "r"(a[2]), "r"(a[3]), "r"(b0), "r"(b1));
}

// smem: per stage: Ahi(16K) Alo(16K) Bhi(16K) Blo(16K) = 64KB; 2 stages = 128KB
#define KCH 64
#define TILE_BYTES 16384
#define STAGE_BYTES 65536
#define SMEM_BYTES (2 * STAGE_BYTES)

// ---------------------------------------------------------------------------
// split-bf16 NT GEMM on HMMA: C[m,n] = sum_k A[m,k]*B[n,k]
// OUTMODE 0: fp32 C; OUTMODE 1: bf16 hi/lo C.
// M,N multiples of 128; K multiple of 64.
// ---------------------------------------------------------------------------
template <int OUTMODE>
__global__ __launch_bounds__(256, 1)
void mma_gemm(const __nv_bfloat16* __restrict__ Ahi, const __nv_bfloat16* __restrict__ Alo,
              int lda, long long sA,
              const __nv_bfloat16* __restrict__ Bhi, const __nv_bfloat16* __restrict__ Blo,
              int ldb, long long sB,
              float* __restrict__ Cf, __nv_bfloat16* __restrict__ Chi,
              __nv_bfloat16* __restrict__ Clo, int ldc, long long sC,
              int K)
{
    extern __shared__ __align__(1024) char smem[];
    const int tid  = threadIdx.x;
    const int wid  = tid >> 5;
    const int lane = tid & 31;

    const long long zz = blockIdx.z;
    const __nv_bfloat16* pAhi = Ahi + zz * sA;
    const __nv_bfloat16* pAlo = Alo + zz * sA;
    const __nv_bfloat16* pBhi = Bhi + zz * sB;
    const __nv_bfloat16* pBlo = Blo + zz * sB;

    const int m0 = blockIdx.y * 128;
    const int n0 = blockIdx.x * 128;

    // loader lane mapping (4 iterations x 4 arrays, 16B each)
    // idx = tid + i*256 in [0,1024): row = idx>>3 (0..127), chunk c = idx&7
    // swizzled offset = row*128 + ((c ^ (row&7))<<4)
    uint32_t s_off[4];
    int g_row[4], g_col[4];
#pragma unroll
    for (int i = 0; i < 4; i++) {
        const int idx = tid + (i << 8);
        const int row = idx >> 3;
        const int c   = idx & 7;
        s_off[i] = (uint32_t)(row * 128 + (((c ^ (row & 7)) & 7) << 4));
        g_row[i] = row;
        g_col[i] = c * 8;
    }

    const int nkt = K / KCH;

    auto load_stage = [&](int kt, int buf) {
        char* sb = smem + buf * STAGE_BYTES;
        const uint32_t sb32 = smem_u32(sb);
        const int kb = kt * KCH;
#pragma unroll
        for (int i = 0; i < 4; i++) {
            const long long ga = (long long)(m0 + g_row[i]) * lda + kb + g_col[i];
            const long long gb = (long long)(n0 + g_row[i]) * ldb + kb + g_col[i];
            cp_async16(sb32 + s_off[i],                     pAhi + ga);
            cp_async16(sb32 + TILE_BYTES + s_off[i],        pAlo + ga);
            cp_async16(sb32 + 2 * TILE_BYTES + s_off[i],    pBhi + gb);
            cp_async16(sb32 + 3 * TILE_BYTES + s_off[i],    pBlo + gb);
        }
        cp_commit();
    };

    // accumulators: warp tile 64x32 -> 4 m-tiles x 4 n-tiles x 4 regs
    float acc[4][4][4];
#pragma unroll
    for (int a = 0; a < 4; a++)
#pragma unroll
        for (int b = 0; b < 4; b++)
#pragma unroll
            for (int c = 0; c < 4; c++) acc[a][b][c] = 0.0f;

    const int wm = wid >> 2;    // 0..1 -> m offset 64*wm
    const int wn = wid & 3;     // 0..3 -> n offset 32*wn
    const int r8 = lane & 7;
    const int aRowSel = (lane >> 3) & 1;   // matid&1 -> +8 rows
    const int aChkSel = (lane >> 4) & 1;   // matid>>1 -> +1 chunk
    // B x4 load: row(n) = base + (matid>>1)*8 + r8 ; chunk = kc + (matid&1)
    const int bRowSel = (lane >> 4) & 1;
    const int bChkSel = (lane >> 3) & 1;

    load_stage(0, 0);

    for (int kt = 0; kt < nkt; kt++) {
        const int buf = kt & 1;
        if (kt + 1 < nkt) { load_stage(kt + 1, buf ^ 1); cp_wait<1>(); }
        else              { cp_wait<0>(); }
        __syncthreads();

        const uint32_t aB = smem_u32(smem + buf * STAGE_BYTES);
        const uint32_t bB = aB + 2 * TILE_BYTES;

#pragma unroll
        for (int h = 0; h < 4; h++) {       // four k16 steps per stage
            const int kc = 2 * h;
            // B fragments: 2 pairs x (hi,lo)
            uint32_t bh[8], bl[8];
#pragma unroll
            for (int p = 0; p < 2; p++) {
                const int brow = wn * 32 + p * 16 + bRowSel * 8 + r8;
                const int bchk = kc + bChkSel;
                const uint32_t ad = bB + brow * 128 + (((bchk ^ (brow & 7)) & 7) << 4);
                ldsm4(&bh[p * 4], ad);
                ldsm4(&bl[p * 4], ad + TILE_BYTES);
            }
#pragma unroll
            for (int mt = 0; mt < 4; mt++) {
                const int arow = wm * 64 + mt * 16 + aRowSel * 8 + r8;
                const int achk = kc + aChkSel;
                const uint32_t ad = aB + arow * 128 + (((achk ^ (arow & 7)) & 7) << 4);
                uint32_t ah[4], al[4];
                ldsm4(ah, ad);
                ldsm4(al, ad + TILE_BYTES);
#pragma unroll
                for (int nt = 0; nt < 4; nt++) {
                    const int p  = nt >> 1;
                    const int of = (nt & 1) * 2;
                    const uint32_t h0 = bh[p * 4 + of], h1 = bh[p * 4 + of + 1];
                    const uint32_t l0 = bl[p * 4 + of], l1 = bl[p * 4 + of + 1];
                    mma16816(acc[mt][nt], ah, h0, h1);   // hi*hi
                    mma16816(acc[mt][nt], ah, l0, l1);   // hi*lo
                    mma16816(acc[mt][nt], al, h0, h1);   // lo*hi
                }
            }
        }
        __syncthreads();
    }

    // epilogue: fragment (mt,nt): rows r,r+8 ; cols c,c+1
    const int er = (lane >> 2);
    const int ec = (lane & 3) * 2;
#pragma unroll
    for (int mt = 0; mt < 4; mt++) {
#pragma unroll
        for (int nt = 0; nt < 4; nt++) {
            const int row = m0 + wm * 64 + mt * 16 + er;
            const int col = n0 + wn * 32 + nt * 8 + ec;
            float* a = acc[mt][nt];
            if (OUTMODE == 0) {
                float* base = Cf + zz * sC;
                float2 v0 = make_float2(a[0], a[1]);
                float2 v1 = make_float2(a[2], a[3]);
                *(float2*)(base + (long long)row * ldc + col)       = v0;
                *(float2*)(base + (long long)(row + 8) * ldc + col) = v1;
            } else {
                const long long o0 = zz * sC + (long long)row * ldc + col;
                const long long o1 = zz * sC + (long long)(row + 8) * ldc + col;
                __nv_bfloat16 h0 = __float2bfloat16(a[0]);
                __nv_bfloat16 h1 = __float2bfloat16(a[1]);
                __nv_bfloat16 h2 = __float2bfloat16(a[2]);
                __nv_bfloat16 h3 = __float2bfloat16(a[3]);
                __nv_bfloat16 l0 = __float2bfloat16(a[0] - __bfloat162float(h0));
                __nv_bfloat16 l1 = __float2bfloat16(a[1] - __bfloat162float(h1));
                __nv_bfloat16 l2 = __float2bfloat16(a[2] - __bfloat162float(h2));
                __nv_bfloat16 l3 = __float2bfloat16(a[3] - __bfloat162float(h3));
                __nv_bfloat162 hv0; hv0.x = h0; hv0.y = h1;
                __nv_bfloat162 hv1; hv1.x = h2; hv1.y = h3;
                __nv_bfloat162 lv0; lv0.x = l0; lv0.y = l1;
                __nv_bfloat162 lv1; lv1.x = l2; lv1.y = l3;
                *(__nv_bfloat162*)(Chi + o0) = hv0;
                *(__nv_bfloat162*)(Chi + o1) = hv1;
                *(__nv_bfloat162*)(Clo + o0) = lv0;
                *(__nv_bfloat162*)(Clo + o1) = lv1;
            }
        }
    }
}

// ---------------------------------------------------------------------------
// fp32 -> bf16 hi/lo split
// ---------------------------------------------------------------------------
__global__ __launch_bounds__(256)
void split_kernel(const float* __restrict__ x, __nv_bfloat16* __restrict__ hi,
                  __nv_bfloat16* __restrict__ lo, int n4)
{
    const int i = blockIdx.x * 256 + threadIdx.x;
    if (i >= n4) return;
    float4 v = ((const float4*)x)[i];
    __nv_bfloat16 h0 = __float2bfloat16(v.x), h1 = __float2bfloat16(v.y);
    __nv_bfloat16 h2 = __float2bfloat16(v.z), h3 = __float2bfloat16(v.w);
    __nv_bfloat16 l0 = __float2bfloat16(v.x - __bfloat162float(h0));
    __nv_bfloat16 l1 = __float2bfloat16(v.y - __bfloat162float(h1));
    __nv_bfloat16 l2 = __float2bfloat16(v.z - __bfloat162float(h2));
    __nv_bfloat16 l3 = __float2bfloat16(v.w - __bfloat162float(h3));
    __nv_bfloat162 a, b, c, d;
    a.x = h0; a.y = h1; b.x = h2; b.y = h3;
    c.x = l0; c.y = l1; d.x = l2; d.y = l3;
    ((__nv_bfloat162*)hi)[i * 2]     = a;
    ((__nv_bfloat162*)hi)[i * 2 + 1] = b;
    ((__nv_bfloat162*)lo)[i * 2]     = c;
    ((__nv_bfloat162*)lo)[i * 2 + 1] = d;
}

// ---------------------------------------------------------------------------
// Row softmax (scale folded), emits bf16 hi/lo probabilities
// ---------------------------------------------------------------------------
__global__ __launch_bounds__(256)
void softmax_split_kernel(const float* __restrict__ scores,
                          __nv_bfloat16* __restrict__ ph, __nv_bfloat16* __restrict__ pl)
{
    const float scale = 0.04419417382415922f; // 1/sqrt(512)
    const long long rowoff = (long long)blockIdx.x * SS;
    const float* p = scores + rowoff;
    const int tid = threadIdx.x;
    const int lane = tid & 31;
    const int warp = tid >> 5;

    __shared__ float red_max[8];
    __shared__ float red_sum[8];

    float4 v[4];
    float m = -3.4e38f;
#pragma unroll
    for (int i = 0; i < 4; i++) {
        v[i] = ((const float4*)p)[tid + 256 * i];
        v[i].x *= scale; v[i].y *= scale; v[i].z *= scale; v[i].w *= scale;
        m = fmaxf(m, fmaxf(fmaxf(v[i].x, v[i].y), fmaxf(v[i].z, v[i].w)));
    }
#pragma unroll
    for (int off = 16; off > 0; off >>= 1)
        m = fmaxf(m, __shfl_xor_sync(0xffffffffu, m, off));
    if (lane == 0) red_max[warp] = m;
    __syncthreads();
    float gm = red_max[0];
#pragma unroll
    for (int w = 1; w < 8; w++) gm = fmaxf(gm, red_max[w]);

    float s = 0.0f;
#pragma unroll
    for (int i = 0; i < 4; i++) {
        v[i].x = expf(v[i].x - gm);
        v[i].y = expf(v[i].y - gm);
        v[i].z = expf(v[i].z - gm);
        v[i].w = expf(v[i].w - gm);
        s += v[i].x + v[i].y + v[i].z + v[i].w;
    }
#pragma unroll
    for (int off = 16; off > 0; off >>= 1)
        s += __shfl_xor_sync(0xffffffffu, s, off);
    if (lane == 0) red_sum[warp] = s;
    __syncthreads();
    float gs = 0.0f;
#pragma unroll
    for (int w = 0; w < 8; w++) gs += red_sum[w];

    const float inv = 1.0f / gs;
#pragma unroll
    for (int i = 0; i < 4; i++) {
        const int f = tid + 256 * i;
        float x0 = v[i].x * inv, x1 = v[i].y * inv, x2 = v[i].z * inv, x3 = v[i].w * inv;
        __nv_bfloat16 h0 = __float2bfloat16(x0), h1 = __float2bfloat16(x1);
        __nv_bfloat16 h2 = __float2bfloat16(x2), h3 = __float2bfloat16(x3);
        __nv_bfloat16 l0 = __float2bfloat16(x0 - __bfloat162float(h0));
        __nv_bfloat16 l1 = __float2bfloat16(x1 - __bfloat162float(h1));
        __nv_bfloat16 l2 = __float2bfloat16(x2 - __bfloat162float(h2));
        __nv_bfloat16 l3 = __float2bfloat16(x3 - __bfloat162float(h3));
        __nv_bfloat162 a, b, c, d;
        a.x = h0; a.y = h1; b.x = h2; b.y = h3;
        c.x = l0; c.y = l1; d.x = l2; d.y = l3;
        ((__nv_bfloat162*)(ph + rowoff))[f * 2]     = a;
        ((__nv_bfloat162*)(ph + rowoff))[f * 2 + 1] = b;
        ((__nv_bfloat162*)(pl + rowoff))[f * 2]     = c;
        ((__nv_bfloat162*)(pl + rowoff))[f * 2 + 1] = d;
    }
}

// ---------------------------------------------------------------------------
extern "C" void kernel_launch(void* const* d_in, const int* in_sizes, int n_in,
                              void* d_out, int out_size)
{
    const float* token = (const float*)d_in[0];
    const float* W1    = (const float*)d_in[1];
    const float* W2    = (const float*)d_in[2];
    const float* W3    = (const float*)d_in[3];
    float*       out   = (float*)d_out;

    __nv_bfloat16 *thi, *tlo, *w1h, *w1l, *w2h, *w2l, *w3h, *w3l;
    __nv_bfloat16 *qhi, *qlo, *khi, *klo, *vth, *vtl, *phi, *plo;
    float* sc;
    cudaGetSymbolAddress((void**)&thi, g_thi);  cudaGetSymbolAddress((void**)&tlo, g_tlo);
    cudaGetSymbolAddress((void**)&w1h, g_w1hi); cudaGetSymbolAddress((void**)&w1l, g_w1lo);
    cudaGetSymbolAddress((void**)&w2h, g_w2hi); cudaGetSymbolAddress((void**)&w2l, g_w2lo);
    cudaGetSymbolAddress((void**)&w3h, g_w3hi); cudaGetSymbolAddress((void**)&w3l, g_w3lo);
    cudaGetSymbolAddress((void**)&qhi, g_qhi);  cudaGetSymbolAddress((void**)&qlo, g_qlo);
    cudaGetSymbolAddress((void**)&khi, g_khi);  cudaGetSymbolAddress((void**)&klo, g_klo);
    cudaGetSymbolAddress((void**)&vth, g_vthi); cudaGetSymbolAddress((void**)&vtl, g_vtlo);
    cudaGetSymbolAddress((void**)&phi, g_phi);  cudaGetSymbolAddress((void**)&plo, g_plo);
    cudaGetSymbolAddress((void**)&sc,  g_sc);

    cudaFuncSetAttribute(mma_gemm<0>, cudaFuncAttributeMaxDynamicSharedMemorySize, SMEM_BYTES);
    cudaFuncSetAttribute(mma_gemm<1>, cudaFuncAttributeMaxDynamicSharedMemorySize, SMEM_BYTES);

    // 1. split inputs into bf16 hi/lo
    split_kernel<<<(BB * SS * DD / 4 + 255) / 256, 256>>>(token, thi, tlo, BB * SS * DD / 4);
    split_kernel<<<(DD * DD / 4 + 255) / 256, 256>>>(W1, w1h, w1l, DD * DD / 4);
    split_kernel<<<(DD * DD / 4 + 255) / 256, 256>>>(W2, w2h, w2l, DD * DD / 4);
    split_kernel<<<(DD * DD / 4 + 255) / 256, 256>>>(W3, w3h, w3l, DD * DD / 4);

    // 2. Q = token @ W1^T   [16384,512]
    mma_gemm<1><<<dim3(DD / 128, BB * SS / 128, 1), 256, SMEM_BYTES>>>(
        thi, tlo, DD, 0, w1h, w1l, DD, 0, nullptr, qhi, qlo, DD, 0, DD);
    // 3. K = token @ W2^T
    mma_gemm<1><<<dim3(DD / 128, BB * SS / 128, 1), 256, SMEM_BYTES>>>(
        thi, tlo, DD, 0, w2h, w2l, DD, 0, nullptr, khi, klo, DD, 0, DD);
    // 4. VT = W3 @ token^T  [512, 16384]
    mma_gemm<1><<<dim3(BB * SS / 128, DD / 128, 1), 256, SMEM_BYTES>>>(
        w3h, w3l, DD, 0, thi, tlo, DD, 0, nullptr, vth, vtl, BB * SS, 0, DD);
    // 5. logits = Q @ K^T per batch
    mma_gemm<0><<<dim3(SS / 128, SS / 128, BB), 256, SMEM_BYTES>>>(
        qhi, qlo, DD, (long long)SS * DD, khi, klo, DD, (long long)SS * DD,
        sc, nullptr, nullptr, SS, (long long)SS * SS, DD);
    // 6. softmax + split
    softmax_split_kernel<<<BB * SS, 256>>>(sc, phi, plo);
    // 7. out = P @ VT^T per batch
    mma_gemm<0><<<dim3(DD / 128, SS / 128, BB), 256, SMEM_BYTES>>>(
        phi, plo, SS, (long long)SS * SS, vth, vtl, BB * SS, (long long)SS,
        out, nullptr, nullptr, DD, (long long)SS * DD, SS);
}

// round 4
// speedup vs baseline: 3.0313x; 1.0084x over previous
#include <cuda_runtime.h>
#include <cuda_bf16.h>
#include <math.h>
#include <stdint.h>

#define BB 4
#define SS 4096
#define DD 512

// ---------------- scratch (static device globals) ----------------
__device__ __nv_bfloat16 g_thi[BB * SS * DD];
__device__ __nv_bfloat16 g_tlo[BB * SS * DD];
__device__ __nv_bfloat16 g_w1hi[DD * DD];
__device__ __nv_bfloat16 g_w1lo[DD * DD];
__device__ __nv_bfloat16 g_w2hi[DD * DD];
__device__ __nv_bfloat16 g_w2lo[DD * DD];
__device__ __nv_bfloat16 g_w3hi[DD * DD];
__device__ __nv_bfloat16 g_w3lo[DD * DD];
__device__ __nv_bfloat16 g_qhi[BB * SS * DD];
__device__ __nv_bfloat16 g_qlo[BB * SS * DD];
__device__ __nv_bfloat16 g_khi[BB * SS * DD];
__device__ __nv_bfloat16 g_klo[BB * SS * DD];
__device__ __nv_bfloat16 g_vthi[DD * BB * SS];   // V^T [DD, BB*SS]
__device__ __nv_bfloat16 g_vtlo[DD * BB * SS];
__device__ float         g_sc [(size_t)BB * SS * SS];
__device__ __nv_bfloat16 g_phi[(size_t)BB * SS * SS];
__device__ __nv_bfloat16 g_plo[(size_t)BB * SS * SS];

// ---------------- PTX helpers (baseline ISA, sm_80-class) ----------------
__device__ __forceinline__ uint32_t smem_u32(const void* p) {
    return (uint32_t)__cvta_generic_to_shared(p);
}
__device__ __forceinline__ void cp_async16(uint32_t s, const void* g) {
    asm volatile("cp.async.cg.shared.global [%0], [%1], 16;" :: "r"(s), "l"(g));
}
__device__ __forceinline__ void cp_commit() {
    asm volatile("cp.async.commit_group;" ::: "memory");
}
template <int N>
__device__ __forceinline__ void cp_wait() {
    asm volatile("cp.async.wait_group %0;" :: "n"(N) : "memory");
}
__device__ __forceinline__ void ldsm4(uint32_t* r, uint32_t addr) {
    asm volatile("ldmatrix.sync.aligned.m8n8.x4.shared.b16 {%0,%1,%2,%3}, [%4];"
                 : "=r"(r[0]), "=r"(r[1]), "=r"(r[2]), "=r"(r[3]) : "r"(addr));
}
__device__ __forceinline__ void mma16816(float* d, const uint32_t* a, uint32_t b0, uint32_t b1) {
    asm volatile("mma.sync.aligned.m16n8k16.row.col.f32.bf16.bf16.f32 "
                 "{%0,%1,%2,%3}, {%4,%5,%6,%7}, {%8,%9}, {%0,%1,%2,%3};"
                 : "+f"(d[0]), "+f"(d[1]), "+f"(d[2]), "+f"(d[3])
                 : "r"(a[0]), "r"(a[1]), "r"(a[2]), "r"(a[3]), "r"(b0), "r"(b1));
}

// K-chunk 32: tile row = 32 bf16 = 64 B = 4 chunks of 16 B.
// swizzle: chunk' = chunk ^ ((row>>1)&3)  -> 8 rows x 4 chunks hit all 32 banks.
#define KCH 32
#define TILE_BYTES 8192                    // 128 rows x 64 B
#define STAGE_BYTES 32768                  // Ahi Alo Bhi Blo
#define NSTAGE 3
#define SMEM_BYTES (NSTAGE * STAGE_BYTES)  // 96 KB -> 2 CTAs/SM

__device__ __forceinline__ uint32_t swz(int row, int chunk) {
    return (uint32_t)(row * 64 + (((chunk ^ ((row >> 1) & 3)) & 3) << 4));
}

// ---------------------------------------------------------------------------
// split-bf16 NT GEMM on HMMA: C[m,n] = sum_k A[m,k]*B[n,k]
// OUTMODE 0: fp32 C; OUTMODE 1: bf16 hi/lo C.
// M,N multiples of 128; K multiple of 32.
// ---------------------------------------------------------------------------
template <int OUTMODE>
__global__ __launch_bounds__(256, 2)
void mma_gemm(const __nv_bfloat16* __restrict__ Ahi, const __nv_bfloat16* __restrict__ Alo,
              int lda, long long sA,
              const __nv_bfloat16* __restrict__ Bhi, const __nv_bfloat16* __restrict__ Blo,
              int ldb, long long sB,
              float* __restrict__ Cf, __nv_bfloat16* __restrict__ Chi,
              __nv_bfloat16* __restrict__ Clo, int ldc, long long sC,
              int K)
{
    extern __shared__ __align__(1024) char smem[];
    const int tid  = threadIdx.x;
    const int wid  = tid >> 5;
    const int lane = tid & 31;

    const long long zz = blockIdx.z;
    const __nv_bfloat16* pAhi = Ahi + zz * sA;
    const __nv_bfloat16* pAlo = Alo + zz * sA;
    const __nv_bfloat16* pBhi = Bhi + zz * sB;
    const __nv_bfloat16* pBlo = Blo + zz * sB;

    const int m0 = blockIdx.y * 128;
    const int n0 = blockIdx.x * 128;

    // loader: 2 iterations, idx = tid + i*256 in [0,512): row = idx>>2, chunk = idx&3
    uint32_t s_off[2];
    int g_row[2], g_col[2];
#pragma unroll
    for (int i = 0; i < 2; i++) {
        const int idx = tid + (i << 8);
        const int row = idx >> 2;
        const int c   = idx & 3;
        s_off[i] = swz(row, c);
        g_row[i] = row;
        g_col[i] = c * 8;
    }

    const int nkt = K / KCH;

    auto load_stage = [&](int kt) {
        const uint32_t sb32 = smem_u32(smem) + (uint32_t)((kt % NSTAGE) * STAGE_BYTES);
        const int kb = kt * KCH;
#pragma unroll
        for (int i = 0; i < 2; i++) {
            const long long ga = (long long)(m0 + g_row[i]) * lda + kb + g_col[i];
            const long long gb = (long long)(n0 + g_row[i]) * ldb + kb + g_col[i];
            cp_async16(sb32 + s_off[i],                  pAhi + ga);
            cp_async16(sb32 + TILE_BYTES + s_off[i],     pAlo + ga);
            cp_async16(sb32 + 2 * TILE_BYTES + s_off[i], pBhi + gb);
            cp_async16(sb32 + 3 * TILE_BYTES + s_off[i], pBlo + gb);
        }
        cp_commit();
    };

    float acc[4][4][4];
#pragma unroll
    for (int a = 0; a < 4; a++)
#pragma unroll
        for (int b = 0; b < 4; b++)
#pragma unroll
            for (int c = 0; c < 4; c++) acc[a][b][c] = 0.0f;

    const int wm = wid >> 2;               // m offset 64*wm
    const int wn = wid & 3;                // n offset 32*wn
    const int r8 = lane & 7;
    const int aRowSel = (lane >> 3) & 1;
    const int aChkSel = (lane >> 4) & 1;
    const int bRowSel = (lane >> 4) & 1;
    const int bChkSel = (lane >> 3) & 1;

    load_stage(0);
    load_stage(1);

    for (int kt = 0; kt < nkt; kt++) {
        if (kt + 2 < nkt) load_stage(kt + 2);
        if (kt + 2 < nkt)      cp_wait<2>();
        else if (kt + 1 < nkt) cp_wait<1>();
        else                   cp_wait<0>();
        __syncthreads();

        const uint32_t aB = smem_u32(smem) + (uint32_t)((kt % NSTAGE) * STAGE_BYTES);
        const uint32_t bB = aB + 2 * TILE_BYTES;

#pragma unroll
        for (int h = 0; h < 2; h++) {      // two k16 steps per stage
            const int kc = 2 * h;
            uint32_t bh[8], bl[8];
#pragma unroll
            for (int p = 0; p < 2; p++) {
                const int brow = wn * 32 + p * 16 + bRowSel * 8 + r8;
                const uint32_t ad = bB + swz(brow, kc + bChkSel);
                ldsm4(&bh[p * 4], ad);
                ldsm4(&bl[p * 4], ad + TILE_BYTES);
            }
#pragma unroll
            for (int mt = 0; mt < 4; mt++) {
                const int arow = wm * 64 + mt * 16 + aRowSel * 8 + r8;
                const uint32_t ad = aB + swz(arow, kc + aChkSel);
                uint32_t ah[4], al[4];
                ldsm4(ah, ad);
                ldsm4(al, ad + TILE_BYTES);
#pragma unroll
                for (int nt = 0; nt < 4; nt++) {
                    const int p  = nt >> 1;
                    const int of = (nt & 1) * 2;
                    const uint32_t h0 = bh[p * 4 + of], h1 = bh[p * 4 + of + 1];
                    const uint32_t l0 = bl[p * 4 + of], l1 = bl[p * 4 + of + 1];
                    mma16816(acc[mt][nt], ah, h0, h1);   // hi*hi
                    mma16816(acc[mt][nt], ah, l0, l1);   // hi*lo
                    mma16816(acc[mt][nt], al, h0, h1);   // lo*hi
                }
            }
        }
        __syncthreads();
    }

    // epilogue
    const int er = (lane >> 2);
    const int ec = (lane & 3) * 2;
#pragma unroll
    for (int mt = 0; mt < 4; mt++) {
#pragma unroll
        for (int nt = 0; nt < 4; nt++) {
            const int row = m0 + wm * 64 + mt * 16 + er;
            const int col = n0 + wn * 32 + nt * 8 + ec;
            float* a = acc[mt][nt];
            if (OUTMODE == 0) {
                float* base = Cf + zz * sC;
                *(float2*)(base + (long long)row * ldc + col)       = make_float2(a[0], a[1]);
                *(float2*)(base + (long long)(row + 8) * ldc + col) = make_float2(a[2], a[3]);
            } else {
                const long long o0 = zz * sC + (long long)row * ldc + col;
                const long long o1 = zz * sC + (long long)(row + 8) * ldc + col;
                __nv_bfloat16 h0 = __float2bfloat16(a[0]);
                __nv_bfloat16 h1 = __float2bfloat16(a[1]);
                __nv_bfloat16 h2 = __float2bfloat16(a[2]);
                __nv_bfloat16 h3 = __float2bfloat16(a[3]);
                __nv_bfloat16 l0 = __float2bfloat16(a[0] - __bfloat162float(h0));
                __nv_bfloat16 l1 = __float2bfloat16(a[1] - __bfloat162float(h1));
                __nv_bfloat16 l2 = __float2bfloat16(a[2] - __bfloat162float(h2));
                __nv_bfloat16 l3 = __float2bfloat16(a[3] - __bfloat162float(h3));
                __nv_bfloat162 hv0; hv0.x = h0; hv0.y = h1;
                __nv_bfloat162 hv1; hv1.x = h2; hv1.y = h3;
                __nv_bfloat162 lv0; lv0.x = l0; lv0.y = l1;
                __nv_bfloat162 lv1; lv1.x = l2; lv1.y = l3;
                *(__nv_bfloat162*)(Chi + o0) = hv0;
                *(__nv_bfloat162*)(Chi + o1) = hv1;
                *(__nv_bfloat162*)(Clo + o0) = lv0;
                *(__nv_bfloat162*)(Clo + o1) = lv1;
            }
        }
    }
}

// ---------------------------------------------------------------------------
// fp32 -> bf16 hi/lo split
// ---------------------------------------------------------------------------
__global__ __launch_bounds__(256)
void split_kernel(const float* __restrict__ x, __nv_bfloat16* __restrict__ hi,
                  __nv_bfloat16* __restrict__ lo, int n4)
{
    const int i = blockIdx.x * 256 + threadIdx.x;
    if (i >= n4) return;
    float4 v = ((const float4*)x)[i];
    __nv_bfloat16 h0 = __float2bfloat16(v.x), h1 = __float2bfloat16(v.y);
    __nv_bfloat16 h2 = __float2bfloat16(v.z), h3 = __float2bfloat16(v.w);
    __nv_bfloat16 l0 = __float2bfloat16(v.x - __bfloat162float(h0));
    __nv_bfloat16 l1 = __float2bfloat16(v.y - __bfloat162float(h1));
    __nv_bfloat16 l2 = __float2bfloat16(v.z - __bfloat162float(h2));
    __nv_bfloat16 l3 = __float2bfloat16(v.w - __bfloat162float(h3));
    __nv_bfloat162 a, b, c, d;
    a.x = h0; a.y = h1; b.x = h2; b.y = h3;
    c.x = l0; c.y = l1; d.x = l2; d.y = l3;
    ((__nv_bfloat162*)hi)[i * 2]     = a;
    ((__nv_bfloat162*)hi)[i * 2 + 1] = b;
    ((__nv_bfloat162*)lo)[i * 2]     = c;
    ((__nv_bfloat162*)lo)[i * 2 + 1] = d;
}

// ---------------------------------------------------------------------------
// Row softmax (scale folded), emits bf16 hi/lo probabilities
// ---------------------------------------------------------------------------
__global__ __launch_bounds__(256)
void softmax_split_kernel(const float* __restrict__ scores,
                          __nv_bfloat16* __restrict__ ph, __nv_bfloat16* __restrict__ pl)
{
    const float scale = 0.04419417382415922f; // 1/sqrt(512)
    const long long rowoff = (long long)blockIdx.x * SS;
    const float* p = scores + rowoff;
    const int tid = threadIdx.x;
    const int lane = tid & 31;
    const int warp = tid >> 5;

    __shared__ float red_max[8];
    __shared__ float red_sum[8];

    float4 v[4];
    float m = -3.4e38f;
#pragma unroll
    for (int i = 0; i < 4; i++) {
        v[i] = ((const float4*)p)[tid + 256 * i];
        v[i].x *= scale; v[i].y *= scale; v[i].z *= scale; v[i].w *= scale;
        m = fmaxf(m, fmaxf(fmaxf(v[i].x, v[i].y), fmaxf(v[i].z, v[i].w)));
    }
#pragma unroll
    for (int off = 16; off > 0; off >>= 1)
        m = fmaxf(m, __shfl_xor_sync(0xffffffffu, m, off));
    if (lane == 0) red_max[warp] = m;
    __syncthreads();
    float gm = red_max[0];
#pragma unroll
    for (int w = 1; w < 8; w++) gm = fmaxf(gm, red_max[w]);

    float s = 0.0f;
#pragma unroll
    for (int i = 0; i < 4; i++) {
        v[i].x = __expf(v[i].x - gm);
        v[i].y = __expf(v[i].y - gm);
        v[i].z = __expf(v[i].z - gm);
        v[i].w = __expf(v[i].w - gm);
        s += v[i].x + v[i].y + v[i].z + v[i].w;
    }
#pragma unroll
    for (int off = 16; off > 0; off >>= 1)
        s += __shfl_xor_sync(0xffffffffu, s, off);
    if (lane == 0) red_sum[warp] = s;
    __syncthreads();
    float gs = 0.0f;
#pragma unroll
    for (int w = 0; w < 8; w++) gs += red_sum[w];

    const float inv = 1.0f / gs;
#pragma unroll
    for (int i = 0; i < 4; i++) {
        const int f = tid + 256 * i;
        float x0 = v[i].x * inv, x1 = v[i].y * inv, x2 = v[i].z * inv, x3 = v[i].w * inv;
        __nv_bfloat16 h0 = __float2bfloat16(x0), h1 = __float2bfloat16(x1);
        __nv_bfloat16 h2 = __float2bfloat16(x2), h3 = __float2bfloat16(x3);
        __nv_bfloat16 l0 = __float2bfloat16(x0 - __bfloat162float(h0));
        __nv_bfloat16 l1 = __float2bfloat16(x1 - __bfloat162float(h1));
        __nv_bfloat16 l2 = __float2bfloat16(x2 - __bfloat162float(h2));
        __nv_bfloat16 l3 = __float2bfloat16(x3 - __bfloat162float(h3));
        __nv_bfloat162 a, b, c, d;
        a.x = h0; a.y = h1; b.x = h2; b.y = h3;
        c.x = l0; c.y = l1; d.x = l2; d.y = l3;
        ((__nv_bfloat162*)(ph + rowoff))[f * 2]     = a;
        ((__nv_bfloat162*)(ph + rowoff))[f * 2 + 1] = b;
        ((__nv_bfloat162*)(pl + rowoff))[f * 2]     = c;
        ((__nv_bfloat162*)(pl + rowoff))[f * 2 + 1] = d;
    }
}

// ---------------------------------------------------------------------------
extern "C" void kernel_launch(void* const* d_in, const int* in_sizes, int n_in,
                              void* d_out, int out_size)
{
    const float* token = (const float*)d_in[0];
    const float* W1    = (const float*)d_in[1];
    const float* W2    = (const float*)d_in[2];
    const float* W3    = (const float*)d_in[3];
    float*       out   = (float*)d_out;

    __nv_bfloat16 *thi, *tlo, *w1h, *w1l, *w2h, *w2l, *w3h, *w3l;
    __nv_bfloat16 *qhi, *qlo, *khi, *klo, *vth, *vtl, *phi, *plo;
    float* sc;
    cudaGetSymbolAddress((void**)&thi, g_thi);  cudaGetSymbolAddress((void**)&tlo, g_tlo);
    cudaGetSymbolAddress((void**)&w1h, g_w1hi); cudaGetSymbolAddress((void**)&w1l, g_w1lo);
    cudaGetSymbolAddress((void**)&w2h, g_w2hi); cudaGetSymbolAddress((void**)&w2l, g_w2lo);
    cudaGetSymbolAddress((void**)&w3h, g_w3hi); cudaGetSymbolAddress((void**)&w3l, g_w3lo);
    cudaGetSymbolAddress((void**)&qhi, g_qhi);  cudaGetSymbolAddress((void**)&qlo, g_qlo);
    cudaGetSymbolAddress((void**)&khi, g_khi);  cudaGetSymbolAddress((void**)&klo, g_klo);
    cudaGetSymbolAddress((void**)&vth, g_vthi); cudaGetSymbolAddress((void**)&vtl, g_vtlo);
    cudaGetSymbolAddress((void**)&phi, g_phi);  cudaGetSymbolAddress((void**)&plo, g_plo);
    cudaGetSymbolAddress((void**)&sc,  g_sc);

    cudaFuncSetAttribute(mma_gemm<0>, cudaFuncAttributeMaxDynamicSharedMemorySize, SMEM_BYTES);
    cudaFuncSetAttribute(mma_gemm<1>, cudaFuncAttributeMaxDynamicSharedMemorySize, SMEM_BYTES);

    // 1. split inputs into bf16 hi/lo
    split_kernel<<<(BB * SS * DD / 4 + 255) / 256, 256>>>(token, thi, tlo, BB * SS * DD / 4);
    split_kernel<<<(DD * DD / 4 + 255) / 256, 256>>>(W1, w1h, w1l, DD * DD / 4);
    split_kernel<<<(DD * DD / 4 + 255) / 256, 256>>>(W2, w2h, w2l, DD * DD / 4);
    split_kernel<<<(DD * DD / 4 + 255) / 256, 256>>>(W3, w3h, w3l, DD * DD / 4);

    // 2. Q = token @ W1^T   [16384,512]
    mma_gemm<1><<<dim3(DD / 128, BB * SS / 128, 1), 256, SMEM_BYTES>>>(
        thi, tlo, DD, 0, w1h, w1l, DD, 0, nullptr, qhi, qlo, DD, 0, DD);
    // 3. K = token @ W2^T
    mma_gemm<1><<<dim3(DD / 128, BB * SS / 128, 1), 256, SMEM_BYTES>>>(
        thi, tlo, DD, 0, w2h, w2l, DD, 0, nullptr, khi, klo, DD, 0, DD);
    // 4. VT = W3 @ token^T  [512, 16384]
    mma_gemm<1><<<dim3(BB * SS / 128, DD / 128, 1), 256, SMEM_BYTES>>>(
        w3h, w3l, DD, 0, thi, tlo, DD, 0, nullptr, vth, vtl, BB * SS, 0, DD);
    // 5. logits = Q @ K^T per batch
    mma_gemm<0><<<dim3(SS / 128, SS / 128, BB), 256, SMEM_BYTES>>>(
        qhi, qlo, DD, (long long)SS * DD, khi, klo, DD, (long long)SS * DD,
        sc, nullptr, nullptr, SS, (long long)SS * SS, DD);
    // 6. softmax + split
    softmax_split_kernel<<<BB * SS, 256>>>(sc, phi, plo);
    // 7. out = P @ VT^T per batch
    mma_gemm<0><<<dim3(DD / 128, SS / 128, BB), 256, SMEM_BYTES>>>(
        phi, plo, SS, (long long)SS * SS, vth, vtl, BB * SS, (long long)SS,
        out, nullptr, nullptr, DD, (long long)SS * DD, SS);
}

// round 5
// speedup vs baseline: 4.0587x; 1.3389x over previous
#include <cuda_runtime.h>
#include <cuda_fp16.h>
#include <math.h>
#include <stdint.h>

#define BB 4
#define SS 4096
#define DD 512

// ---------------- scratch (static device globals) ----------------
__device__ __half g_thi[BB * SS * DD];             // token hi (also single-fp16 token)
__device__ __half g_tlo[BB * SS * DD];             // token lo
__device__ __half g_w1h[DD * DD];                  // W1 single
__device__ __half g_w2h[DD * DD];                  // W2 single
__device__ __half g_w3h[DD * DD];                  // W3 hi
__device__ __half g_w3l[DD * DD];                  // W3 lo
__device__ __half g_qhi[BB * SS * DD];
__device__ __half g_qlo[BB * SS * DD];
__device__ __half g_k  [BB * SS * DD];             // K single
__device__ __half g_vt [DD * BB * SS];             // V^T single [DD, BB*SS]
__device__ float  g_sc [(size_t)BB * SS * SS];
__device__ __half g_phi[(size_t)BB * SS * SS];
__device__ __half g_plo[(size_t)BB * SS * SS];

// ---------------- PTX helpers (baseline ISA, sm_80-class) ----------------
__device__ __forceinline__ uint32_t smem_u32(const void* p) {
    return (uint32_t)__cvta_generic_to_shared(p);
}
__device__ __forceinline__ void cp_async16(uint32_t s, const void* g) {
    asm volatile("cp.async.cg.shared.global [%0], [%1], 16;" :: "r"(s), "l"(g));
}
__device__ __forceinline__ void cp_commit() {
    asm volatile("cp.async.commit_group;" ::: "memory");
}
template <int N>
__device__ __forceinline__ void cp_wait() {
    asm volatile("cp.async.wait_group %0;" :: "n"(N) : "memory");
}
__device__ __forceinline__ void ldsm4(uint32_t* r, uint32_t addr) {
    asm volatile("ldmatrix.sync.aligned.m8n8.x4.shared.b16 {%0,%1,%2,%3}, [%4];"
                 : "=r"(r[0]), "=r"(r[1]), "=r"(r[2]), "=r"(r[3]) : "r"(addr));
}
__device__ __forceinline__ void mma16816(float* d, const uint32_t* a, uint32_t b0, uint32_t b1) {
    asm volatile("mma.sync.aligned.m16n8k16.row.col.f32.f16.f16.f32 "
                 "{%0,%1,%2,%3}, {%4,%5,%6,%7}, {%8,%9}, {%0,%1,%2,%3};"
                 : "+f"(d[0]), "+f"(d[1]), "+f"(d[2]), "+f"(d[3])
                 : "r"(a[0]), "r"(a[1]), "r"(a[2]), "r"(a[3]), "r"(b0), "r"(b1));
}

// K-chunk 32: tile row = 32 fp16 = 64 B = 4 chunks of 16 B.
#define KCH 32
#define TILE_BYTES 8192                    // 128 rows x 64 B
#define STAGE_BYTES 24576                  // Ahi Alo B
#define NSTAGE 3
#define SMEM_BYTES (NSTAGE * STAGE_BYTES)  // 72 KB -> 2 CTAs/SM

__device__ __forceinline__ uint32_t swz(int row, int chunk) {
    return (uint32_t)(row * 64 + (((chunk ^ ((row >> 1) & 3)) & 3) << 4));
}

__device__ __forceinline__ void split2(float x, __half& h, __half& l) {
    h = __float2half_rn(x);
    l = __float2half_rn(x - __half2float(h));
}

// ---------------------------------------------------------------------------
// split-fp16 NT GEMM on HMMA: C[m,n] = sum_k A[m,k]*B[n,k]
//   A = Ah + Al (fp16 pair), B = single fp16.  2 MMAs per logical MMA.
// OUTMODE 0: fp32 C; OUTMODE 1: fp16 hi/lo C; OUTMODE 2: fp16 single C.
// M,N multiples of 128; K multiple of 32.
// ---------------------------------------------------------------------------
template <int OUTMODE>
__global__ __launch_bounds__(256, 2)
void mma_gemm(const __half* __restrict__ Ahi, const __half* __restrict__ Alo,
              int lda, long long sA,
              const __half* __restrict__ Bs, int ldb, long long sB,
              float* __restrict__ Cf, __half* __restrict__ Chi,
              __half* __restrict__ Clo, int ldc, long long sC,
              int K)
{
    extern __shared__ __align__(1024) char smem[];
    const int tid  = threadIdx.x;
    const int wid  = tid >> 5;
    const int lane = tid & 31;

    const long long zz = blockIdx.z;
    const __half* pAhi = Ahi + zz * sA;
    const __half* pAlo = Alo + zz * sA;
    const __half* pB   = Bs  + zz * sB;

    const int m0 = blockIdx.y * 128;
    const int n0 = blockIdx.x * 128;

    uint32_t s_off[2];
    int g_row[2], g_col[2];
#pragma unroll
    for (int i = 0; i < 2; i++) {
        const int idx = tid + (i << 8);
        const int row = idx >> 2;
        const int c   = idx & 3;
        s_off[i] = swz(row, c);
        g_row[i] = row;
        g_col[i] = c * 8;
    }

    const int nkt = K / KCH;

    auto load_stage = [&](int kt) {
        const uint32_t sb32 = smem_u32(smem) + (uint32_t)((kt % NSTAGE) * STAGE_BYTES);
        const int kb = kt * KCH;
#pragma unroll
        for (int i = 0; i < 2; i++) {
            const long long ga = (long long)(m0 + g_row[i]) * lda + kb + g_col[i];
            const long long gb = (long long)(n0 + g_row[i]) * ldb + kb + g_col[i];
            cp_async16(sb32 + s_off[i],                  pAhi + ga);
            cp_async16(sb32 + TILE_BYTES + s_off[i],     pAlo + ga);
            cp_async16(sb32 + 2 * TILE_BYTES + s_off[i], pB + gb);
        }
        cp_commit();
    };

    float acc[4][4][4];
#pragma unroll
    for (int a = 0; a < 4; a++)
#pragma unroll
        for (int b = 0; b < 4; b++)
#pragma unroll
            for (int c = 0; c < 4; c++) acc[a][b][c] = 0.0f;

    const int wm = wid >> 2;               // m offset 64*wm
    const int wn = wid & 3;                // n offset 32*wn
    const int r8 = lane & 7;
    const int aRowSel = (lane >> 3) & 1;
    const int aChkSel = (lane >> 4) & 1;
    const int bRowSel = (lane >> 4) & 1;
    const int bChkSel = (lane >> 3) & 1;

    load_stage(0);
    load_stage(1);

    for (int kt = 0; kt < nkt; kt++) {
        if (kt + 2 < nkt) load_stage(kt + 2);
        if (kt + 2 < nkt)      cp_wait<2>();
        else if (kt + 1 < nkt) cp_wait<1>();
        else                   cp_wait<0>();
        __syncthreads();

        const uint32_t aB = smem_u32(smem) + (uint32_t)((kt % NSTAGE) * STAGE_BYTES);
        const uint32_t bB = aB + 2 * TILE_BYTES;

#pragma unroll
        for (int h = 0; h < 2; h++) {      // two k16 steps per stage
            const int kc = 2 * h;
            uint32_t bfr[8];
#pragma unroll
            for (int p = 0; p < 2; p++) {
                const int brow = wn * 32 + p * 16 + bRowSel * 8 + r8;
                const uint32_t ad = bB + swz(brow, kc + bChkSel);
                ldsm4(&bfr[p * 4], ad);
            }
#pragma unroll
            for (int mt = 0; mt < 4; mt++) {
                const int arow = wm * 64 + mt * 16 + aRowSel * 8 + r8;
                const uint32_t ad = aB + swz(arow, kc + aChkSel);
                uint32_t ah[4], al[4];
                ldsm4(ah, ad);
                ldsm4(al, ad + TILE_BYTES);
#pragma unroll
                for (int nt = 0; nt < 4; nt++) {
                    const int p  = nt >> 1;
                    const int of = (nt & 1) * 2;
                    const uint32_t b0 = bfr[p * 4 + of], b1 = bfr[p * 4 + of + 1];
                    mma16816(acc[mt][nt], ah, b0, b1);   // Ah*B
                    mma16816(acc[mt][nt], al, b0, b1);   // Al*B
                }
            }
        }
        __syncthreads();
    }

    // epilogue
    const int er = (lane >> 2);
    const int ec = (lane & 3) * 2;
#pragma unroll
    for (int mt = 0; mt < 4; mt++) {
#pragma unroll
        for (int nt = 0; nt < 4; nt++) {
            const int row = m0 + wm * 64 + mt * 16 + er;
            const int col = n0 + wn * 32 + nt * 8 + ec;
            float* a = acc[mt][nt];
            const long long o0 = zz * sC + (long long)row * ldc + col;
            const long long o1 = zz * sC + (long long)(row + 8) * ldc + col;
            if (OUTMODE == 0) {
                *(float2*)(Cf + o0) = make_float2(a[0], a[1]);
                *(float2*)(Cf + o1) = make_float2(a[2], a[3]);
            } else if (OUTMODE == 2) {
                __half2 v0, v1;
                v0.x = __float2half_rn(a[0]); v0.y = __float2half_rn(a[1]);
                v1.x = __float2half_rn(a[2]); v1.y = __float2half_rn(a[3]);
                *(__half2*)(Chi + o0) = v0;
                *(__half2*)(Chi + o1) = v1;
            } else {
                __half h0, h1, h2, h3, l0, l1, l2, l3;
                split2(a[0], h0, l0); split2(a[1], h1, l1);
                split2(a[2], h2, l2); split2(a[3], h3, l3);
                __half2 hv0; hv0.x = h0; hv0.y = h1;
                __half2 hv1; hv1.x = h2; hv1.y = h3;
                __half2 lv0; lv0.x = l0; lv0.y = l1;
                __half2 lv1; lv1.x = l2; lv1.y = l3;
                *(__half2*)(Chi + o0) = hv0;
                *(__half2*)(Chi + o1) = hv1;
                *(__half2*)(Clo + o0) = lv0;
                *(__half2*)(Clo + o1) = lv1;
            }
        }
    }
}

// ---------------------------------------------------------------------------
// fp32 -> fp16 hi/lo split
// ---------------------------------------------------------------------------
__global__ __launch_bounds__(256)
void split_kernel(const float* __restrict__ x, __half* __restrict__ hi,
                  __half* __restrict__ lo, int n4)
{
    const int i = blockIdx.x * 256 + threadIdx.x;
    if (i >= n4) return;
    float4 v = ((const float4*)x)[i];
    __half h0, h1, h2, h3, l0, l1, l2, l3;
    split2(v.x, h0, l0); split2(v.y, h1, l1);
    split2(v.z, h2, l2); split2(v.w, h3, l3);
    __half2 a, b, c, d;
    a.x = h0; a.y = h1; b.x = h2; b.y = h3;
    c.x = l0; c.y = l1; d.x = l2; d.y = l3;
    ((__half2*)hi)[i * 2]     = a;
    ((__half2*)hi)[i * 2 + 1] = b;
    ((__half2*)lo)[i * 2]     = c;
    ((__half2*)lo)[i * 2 + 1] = d;
}

// fp32 -> fp16 single round
__global__ __launch_bounds__(256)
void round_kernel(const float* __restrict__ x, __half* __restrict__ h, int n4)
{
    const int i = blockIdx.x * 256 + threadIdx.x;
    if (i >= n4) return;
    float4 v = ((const float4*)x)[i];
    __half2 a, b;
    a.x = __float2half_rn(v.x); a.y = __float2half_rn(v.y);
    b.x = __float2half_rn(v.z); b.y = __float2half_rn(v.w);
    ((__half2*)h)[i * 2]     = a;
    ((__half2*)h)[i * 2 + 1] = b;
}

// ---------------------------------------------------------------------------
// Row softmax (scale folded), emits fp16 hi/lo probabilities
// ---------------------------------------------------------------------------
__global__ __launch_bounds__(256)
void softmax_split_kernel(const float* __restrict__ scores,
                          __half* __restrict__ ph, __half* __restrict__ pl)
{
    const float scale = 0.04419417382415922f; // 1/sqrt(512)
    const long long rowoff = (long long)blockIdx.x * SS;
    const float* p = scores + rowoff;
    const int tid = threadIdx.x;
    const int lane = tid & 31;
    const int warp = tid >> 5;

    __shared__ float red_max[8];
    __shared__ float red_sum[8];

    float4 v[4];
    float m = -3.4e38f;
#pragma unroll
    for (int i = 0; i < 4; i++) {
        v[i] = ((const float4*)p)[tid + 256 * i];
        v[i].x *= scale; v[i].y *= scale; v[i].z *= scale; v[i].w *= scale;
        m = fmaxf(m, fmaxf(fmaxf(v[i].x, v[i].y), fmaxf(v[i].z, v[i].w)));
    }
#pragma unroll
    for (int off = 16; off > 0; off >>= 1)
        m = fmaxf(m, __shfl_xor_sync(0xffffffffu, m, off));
    if (lane == 0) red_max[warp] = m;
    __syncthreads();
    float gm = red_max[0];
#pragma unroll
    for (int w = 1; w < 8; w++) gm = fmaxf(gm, red_max[w]);

    float s = 0.0f;
#pragma unroll
    for (int i = 0; i < 4; i++) {
        v[i].x = __expf(v[i].x - gm);
        v[i].y = __expf(v[i].y - gm);
        v[i].z = __expf(v[i].z - gm);
        v[i].w = __expf(v[i].w - gm);
        s += v[i].x + v[i].y + v[i].z + v[i].w;
    }
#pragma unroll
    for (int off = 16; off > 0; off >>= 1)
        s += __shfl_xor_sync(0xffffffffu, s, off);
    if (lane == 0) red_sum[warp] = s;
    __syncthreads();
    float gs = 0.0f;
#pragma unroll
    for (int w = 0; w < 8; w++) gs += red_sum[w];

    const float inv = 1.0f / gs;
#pragma unroll
    for (int i = 0; i < 4; i++) {
        const int f = tid + 256 * i;
        float x0 = v[i].x * inv, x1 = v[i].y * inv, x2 = v[i].z * inv, x3 = v[i].w * inv;
        __half h0, h1, h2, h3, l0, l1, l2, l3;
        split2(x0, h0, l0); split2(x1, h1, l1);
        split2(x2, h2, l2); split2(x3, h3, l3);
        __half2 a, b, c, d;
        a.x = h0; a.y = h1; b.x = h2; b.y = h3;
        c.x = l0; c.y = l1; d.x = l2; d.y = l3;
        ((__half2*)(ph + rowoff))[f * 2]     = a;
        ((__half2*)(ph + rowoff))[f * 2 + 1] = b;
        ((__half2*)(pl + rowoff))[f * 2]     = c;
        ((__half2*)(pl + rowoff))[f * 2 + 1] = d;
    }
}

// ---------------------------------------------------------------------------
extern "C" void kernel_launch(void* const* d_in, const int* in_sizes, int n_in,
                              void* d_out, int out_size)
{
    const float* token = (const float*)d_in[0];
    const float* W1    = (const float*)d_in[1];
    const float* W2    = (const float*)d_in[2];
    const float* W3    = (const float*)d_in[3];
    float*       out   = (float*)d_out;

    __half *thi, *tlo, *w1h, *w2h, *w3h, *w3l;
    __half *qhi, *qlo, *kk, *vt, *phi, *plo;
    float* sc;
    cudaGetSymbolAddress((void**)&thi, g_thi);  cudaGetSymbolAddress((void**)&tlo, g_tlo);
    cudaGetSymbolAddress((void**)&w1h, g_w1h);  cudaGetSymbolAddress((void**)&w2h, g_w2h);
    cudaGetSymbolAddress((void**)&w3h, g_w3h);  cudaGetSymbolAddress((void**)&w3l, g_w3l);
    cudaGetSymbolAddress((void**)&qhi, g_qhi);  cudaGetSymbolAddress((void**)&qlo, g_qlo);
    cudaGetSymbolAddress((void**)&kk,  g_k);    cudaGetSymbolAddress((void**)&vt,  g_vt);
    cudaGetSymbolAddress((void**)&phi, g_phi);  cudaGetSymbolAddress((void**)&plo, g_plo);
    cudaGetSymbolAddress((void**)&sc,  g_sc);

    cudaFuncSetAttribute(mma_gemm<0>, cudaFuncAttributeMaxDynamicSharedMemorySize, SMEM_BYTES);
    cudaFuncSetAttribute(mma_gemm<1>, cudaFuncAttributeMaxDynamicSharedMemorySize, SMEM_BYTES);
    cudaFuncSetAttribute(mma_gemm<2>, cudaFuncAttributeMaxDynamicSharedMemorySize, SMEM_BYTES);

    // 1. input conversions
    split_kernel<<<BB * SS * DD / 4 / 256, 256>>>(token, thi, tlo, BB * SS * DD / 4);
    round_kernel<<<DD * DD / 4 / 256, 256>>>(W1, w1h, DD * DD / 4);
    round_kernel<<<DD * DD / 4 / 256, 256>>>(W2, w2h, DD * DD / 4);
    split_kernel<<<DD * DD / 4 / 256, 256>>>(W3, w3h, w3l, DD * DD / 4);

    // 2. Q = token @ W1^T  -> fp16 hi/lo
    mma_gemm<1><<<dim3(DD / 128, BB * SS / 128, 1), 256, SMEM_BYTES>>>(
        thi, tlo, DD, 0, w1h, DD, 0, nullptr, qhi, qlo, DD, 0, DD);
    // 3. K = token @ W2^T  -> fp16 single
    mma_gemm<2><<<dim3(DD / 128, BB * SS / 128, 1), 256, SMEM_BYTES>>>(
        thi, tlo, DD, 0, w2h, DD, 0, nullptr, kk, nullptr, DD, 0, DD);
    // 4. VT = W3 @ token^T -> fp16 single  [512, 16384]
    mma_gemm<2><<<dim3(BB * SS / 128, DD / 128, 1), 256, SMEM_BYTES>>>(
        w3h, w3l, DD, 0, thi, DD, 0, nullptr, vt, nullptr, BB * SS, 0, DD);
    // 5. logits = Q @ K^T per batch -> fp32
    mma_gemm<0><<<dim3(SS / 128, SS / 128, BB), 256, SMEM_BYTES>>>(
        qhi, qlo, DD, (long long)SS * DD, kk, DD, (long long)SS * DD,
        sc, nullptr, nullptr, SS, (long long)SS * SS, DD);
    // 6. softmax + split
    softmax_split_kernel<<<BB * SS, 256>>>(sc, phi, plo);
    // 7. out = P @ VT^T per batch -> fp32
    mma_gemm<0><<<dim3(DD / 128, SS / 128, BB), 256, SMEM_BYTES>>>(
        phi, plo, SS, (long long)SS * SS, vt, BB * SS, (long long)SS,
        out, nullptr, nullptr, DD, (long long)SS * DD, SS);
}

// round 6
// speedup vs baseline: 5.0278x; 1.2388x over previous
#include <cuda_runtime.h>
#include <cuda_fp16.h>
#include <math.h>
#include <stdint.h>

#define BB 4
#define SS 4096
#define DD 512

// ---------------- scratch (static device globals) ----------------
__device__ __half g_thi[BB * SS * DD];             // token hi (also single-fp16 token)
__device__ __half g_tlo[BB * SS * DD];             // token lo
__device__ __half g_w1h[DD * DD];                  // W1 single
__device__ __half g_w2h[DD * DD];                  // W2 single
__device__ __half g_w3h[DD * DD];                  // W3 hi
__device__ __half g_w3l[DD * DD];                  // W3 lo
__device__ __half g_qhi[BB * SS * DD];
__device__ __half g_qlo[BB * SS * DD];
__device__ __half g_k  [BB * SS * DD];             // K single
__device__ __half g_vt [DD * BB * SS];             // V^T single [DD, BB*SS]
__device__ float  g_sc [(size_t)BB * SS * SS];
__device__ __half g_p  [(size_t)BB * SS * SS];     // softmax probs, single fp16

// ---------------- PTX helpers (baseline ISA, sm_80-class) ----------------
__device__ __forceinline__ uint32_t smem_u32(const void* p) {
    return (uint32_t)__cvta_generic_to_shared(p);
}
__device__ __forceinline__ void cp_async16(uint32_t s, const void* g) {
    asm volatile("cp.async.cg.shared.global [%0], [%1], 16;" :: "r"(s), "l"(g));
}
__device__ __forceinline__ void cp_commit() {
    asm volatile("cp.async.commit_group;" ::: "memory");
}
template <int N>
__device__ __forceinline__ void cp_wait() {
    asm volatile("cp.async.wait_group %0;" :: "n"(N) : "memory");
}
__device__ __forceinline__ void ldsm4(uint32_t* r, uint32_t addr) {
    asm volatile("ldmatrix.sync.aligned.m8n8.x4.shared.b16 {%0,%1,%2,%3}, [%4];"
                 : "=r"(r[0]), "=r"(r[1]), "=r"(r[2]), "=r"(r[3]) : "r"(addr));
}
__device__ __forceinline__ void mma16816(float* d, const uint32_t* a, uint32_t b0, uint32_t b1) {
    asm volatile("mma.sync.aligned.m16n8k16.row.col.f32.f16.f16.f32 "
                 "{%0,%1,%2,%3}, {%4,%5,%6,%7}, {%8,%9}, {%0,%1,%2,%3};"
                 : "+f"(d[0]), "+f"(d[1]), "+f"(d[2]), "+f"(d[3])
                 : "r"(a[0]), "r"(a[1]), "r"(a[2]), "r"(a[3]), "r"(b0), "r"(b1));
}

// K-chunk 32: tile row = 32 fp16 = 64 B = 4 chunks of 16 B.
#define KCH 32
#define TILE_BYTES 8192                    // 128 rows x 64 B
#define NSTAGE 3

__device__ __forceinline__ uint32_t swz(int row, int chunk) {
    return (uint32_t)(row * 64 + (((chunk ^ ((row >> 1) & 3)) & 3) << 4));
}

__device__ __forceinline__ void split2(float x, __half& h, __half& l) {
    h = __float2half_rn(x);
    l = __float2half_rn(x - __half2float(h));
}

// ---------------------------------------------------------------------------
// split-fp16 NT GEMM on HMMA: C[m,n] = sum_k A[m,k]*B[n,k]
//   NPROD=2: A = Ah + Al (fp16 pair); NPROD=1: A single fp16. B single fp16.
// OUTMODE 0: fp32 C; OUTMODE 1: fp16 hi/lo C; OUTMODE 2: fp16 single C.
// M,N multiples of 128; K multiple of 32.
// ---------------------------------------------------------------------------
template <int OUTMODE, int NPROD>
__global__ __launch_bounds__(256, 2)
void mma_gemm(const __half* __restrict__ Ahi, const __half* __restrict__ Alo,
              int lda, long long sA,
              const __half* __restrict__ Bs, int ldb, long long sB,
              float* __restrict__ Cf, __half* __restrict__ Chi,
              __half* __restrict__ Clo, int ldc, long long sC,
              int K)
{
    constexpr int STAGE_BYTES = (NPROD + 1) * TILE_BYTES;
    extern __shared__ __align__(1024) char smem[];
    const int tid  = threadIdx.x;
    const int wid  = tid >> 5;
    const int lane = tid & 31;

    const long long zz = blockIdx.z;
    const __half* pAhi = Ahi + zz * sA;
    const __half* pAlo = (NPROD == 2) ? (Alo + zz * sA) : nullptr;
    const __half* pB   = Bs  + zz * sB;

    const int m0 = blockIdx.y * 128;
    const int n0 = blockIdx.x * 128;

    uint32_t s_off[2];
    int g_row[2], g_col[2];
#pragma unroll
    for (int i = 0; i < 2; i++) {
        const int idx = tid + (i << 8);
        const int row = idx >> 2;
        const int c   = idx & 3;
        s_off[i] = swz(row, c);
        g_row[i] = row;
        g_col[i] = c * 8;
    }

    const int nkt = K / KCH;

    auto load_stage = [&](int kt) {
        const uint32_t sb32 = smem_u32(smem) + (uint32_t)((kt % NSTAGE) * STAGE_BYTES);
        const int kb = kt * KCH;
#pragma unroll
        for (int i = 0; i < 2; i++) {
            const long long ga = (long long)(m0 + g_row[i]) * lda + kb + g_col[i];
            const long long gb = (long long)(n0 + g_row[i]) * ldb + kb + g_col[i];
            cp_async16(sb32 + s_off[i], pAhi + ga);
            if (NPROD == 2) cp_async16(sb32 + TILE_BYTES + s_off[i], pAlo + ga);
            cp_async16(sb32 + NPROD * TILE_BYTES + s_off[i], pB + gb);
        }
        cp_commit();
    };

    float acc[4][4][4];
#pragma unroll
    for (int a = 0; a < 4; a++)
#pragma unroll
        for (int b = 0; b < 4; b++)
#pragma unroll
            for (int c = 0; c < 4; c++) acc[a][b][c] = 0.0f;

    const int wm = wid >> 2;               // m offset 64*wm
    const int wn = wid & 3;                // n offset 32*wn
    const int r8 = lane & 7;
    const int aRowSel = (lane >> 3) & 1;
    const int aChkSel = (lane >> 4) & 1;
    const int bRowSel = (lane >> 4) & 1;
    const int bChkSel = (lane >> 3) & 1;

    load_stage(0);
    load_stage(1);

    for (int kt = 0; kt < nkt; kt++) {
        if (kt + 2 < nkt) load_stage(kt + 2);
        if (kt + 2 < nkt)      cp_wait<2>();
        else if (kt + 1 < nkt) cp_wait<1>();
        else                   cp_wait<0>();
        __syncthreads();

        const uint32_t aB = smem_u32(smem) + (uint32_t)((kt % NSTAGE) * STAGE_BYTES);
        const uint32_t bB = aB + NPROD * TILE_BYTES;

#pragma unroll
        for (int h = 0; h < 2; h++) {      // two k16 steps per stage
            const int kc = 2 * h;
            uint32_t bfr[8];
#pragma unroll
            for (int p = 0; p < 2; p++) {
                const int brow = wn * 32 + p * 16 + bRowSel * 8 + r8;
                const uint32_t ad = bB + swz(brow, kc + bChkSel);
                ldsm4(&bfr[p * 4], ad);
            }
#pragma unroll
            for (int mt = 0; mt < 4; mt++) {
                const int arow = wm * 64 + mt * 16 + aRowSel * 8 + r8;
                const uint32_t ad = aB + swz(arow, kc + aChkSel);
                uint32_t ah[4], al[4];
                ldsm4(ah, ad);
                if (NPROD == 2) ldsm4(al, ad + TILE_BYTES);
#pragma unroll
                for (int nt = 0; nt < 4; nt++) {
                    const int p  = nt >> 1;
                    const int of = (nt & 1) * 2;
                    const uint32_t b0 = bfr[p * 4 + of], b1 = bfr[p * 4 + of + 1];
                    mma16816(acc[mt][nt], ah, b0, b1);                // Ah*B
                    if (NPROD == 2) mma16816(acc[mt][nt], al, b0, b1); // Al*B
                }
            }
        }
        __syncthreads();
    }

    // epilogue
    const int er = (lane >> 2);
    const int ec = (lane & 3) * 2;
#pragma unroll
    for (int mt = 0; mt < 4; mt++) {
#pragma unroll
        for (int nt = 0; nt < 4; nt++) {
            const int row = m0 + wm * 64 + mt * 16 + er;
            const int col = n0 + wn * 32 + nt * 8 + ec;
            float* a = acc[mt][nt];
            const long long o0 = zz * sC + (long long)row * ldc + col;
            const long long o1 = zz * sC + (long long)(row + 8) * ldc + col;
            if (OUTMODE == 0) {
                *(float2*)(Cf + o0) = make_float2(a[0], a[1]);
                *(float2*)(Cf + o1) = make_float2(a[2], a[3]);
            } else if (OUTMODE == 2) {
                __half2 v0, v1;
                v0.x = __float2half_rn(a[0]); v0.y = __float2half_rn(a[1]);
                v1.x = __float2half_rn(a[2]); v1.y = __float2half_rn(a[3]);
                *(__half2*)(Chi + o0) = v0;
                *(__half2*)(Chi + o1) = v1;
            } else {
                __half h0, h1, h2, h3, l0, l1, l2, l3;
                split2(a[0], h0, l0); split2(a[1], h1, l1);
                split2(a[2], h2, l2); split2(a[3], h3, l3);
                __half2 hv0; hv0.x = h0; hv0.y = h1;
                __half2 hv1; hv1.x = h2; hv1.y = h3;
                __half2 lv0; lv0.x = l0; lv0.y = l1;
                __half2 lv1; lv1.x = l2; lv1.y = l3;
                *(__half2*)(Chi + o0) = hv0;
                *(__half2*)(Chi + o1) = hv1;
                *(__half2*)(Clo + o0) = lv0;
                *(__half2*)(Clo + o1) = lv1;
            }
        }
    }
}

// ---------------------------------------------------------------------------
// fp32 -> fp16 hi/lo split (token)
// ---------------------------------------------------------------------------
__global__ __launch_bounds__(256)
void split_kernel(const float* __restrict__ x, __half* __restrict__ hi,
                  __half* __restrict__ lo, int n4)
{
    const int i = blockIdx.x * 256 + threadIdx.x;
    if (i >= n4) return;
    float4 v = ((const float4*)x)[i];
    __half h0, h1, h2, h3, l0, l1, l2, l3;
    split2(v.x, h0, l0); split2(v.y, h1, l1);
    split2(v.z, h2, l2); split2(v.w, h3, l3);
    __half2 a, b, c, d;
    a.x = h0; a.y = h1; b.x = h2; b.y = h3;
    c.x = l0; c.y = l1; d.x = l2; d.y = l3;
    ((__half2*)hi)[i * 2]     = a;
    ((__half2*)hi)[i * 2 + 1] = b;
    ((__half2*)lo)[i * 2]     = c;
    ((__half2*)lo)[i * 2 + 1] = d;
}

// all three weight conversions in one launch: W1,W2 -> round; W3 -> split
__global__ __launch_bounds__(256)
void wconv_kernel(const float* __restrict__ W1, const float* __restrict__ W2,
                  const float* __restrict__ W3,
                  __half* __restrict__ w1h, __half* __restrict__ w2h,
                  __half* __restrict__ w3h, __half* __restrict__ w3l)
{
    const int n4 = DD * DD / 4;
    const int gi = blockIdx.x * 256 + threadIdx.x;
    const int which = gi / n4;
    const int i = gi - which * n4;
    if (which == 0 || which == 1) {
        const float* W = (which == 0) ? W1 : W2;
        __half* out = (which == 0) ? w1h : w2h;
        float4 v = ((const float4*)W)[i];
        __half2 a, b;
        a.x = __float2half_rn(v.x); a.y = __float2half_rn(v.y);
        b.x = __float2half_rn(v.z); b.y = __float2half_rn(v.w);
        ((__half2*)out)[i * 2]     = a;
        ((__half2*)out)[i * 2 + 1] = b;
    } else {
        float4 v = ((const float4*)W3)[i];
        __half h0, h1, h2, h3, l0, l1, l2, l3;
        split2(v.x, h0, l0); split2(v.y, h1, l1);
        split2(v.z, h2, l2); split2(v.w, h3, l3);
        __half2 a, b, c, d;
        a.x = h0; a.y = h1; b.x = h2; b.y = h3;
        c.x = l0; c.y = l1; d.x = l2; d.y = l3;
        ((__half2*)w3h)[i * 2]     = a;
        ((__half2*)w3h)[i * 2 + 1] = b;
        ((__half2*)w3l)[i * 2]     = c;
        ((__half2*)w3l)[i * 2 + 1] = d;
    }
}

// ---------------------------------------------------------------------------
// Row softmax (scale folded), emits single fp16 probabilities
// ---------------------------------------------------------------------------
__global__ __launch_bounds__(256)
void softmax_kernel(const float* __restrict__ scores, __half* __restrict__ ph)
{
    const float scale = 0.04419417382415922f; // 1/sqrt(512)
    const long long rowoff = (long long)blockIdx.x * SS;
    const float* p = scores + rowoff;
    const int tid = threadIdx.x;
    const int lane = tid & 31;
    const int warp = tid >> 5;

    __shared__ float red_max[8];
    __shared__ float red_sum[8];

    float4 v[4];
    float m = -3.4e38f;
#pragma unroll
    for (int i = 0; i < 4; i++) {
        v[i] = ((const float4*)p)[tid + 256 * i];
        v[i].x *= scale; v[i].y *= scale; v[i].z *= scale; v[i].w *= scale;
        m = fmaxf(m, fmaxf(fmaxf(v[i].x, v[i].y), fmaxf(v[i].z, v[i].w)));
    }
#pragma unroll
    for (int off = 16; off > 0; off >>= 1)
        m = fmaxf(m, __shfl_xor_sync(0xffffffffu, m, off));
    if (lane == 0) red_max[warp] = m;
    __syncthreads();
    float gm = red_max[0];
#pragma unroll
    for (int w = 1; w < 8; w++) gm = fmaxf(gm, red_max[w]);

    float s = 0.0f;
#pragma unroll
    for (int i = 0; i < 4; i++) {
        v[i].x = __expf(v[i].x - gm);
        v[i].y = __expf(v[i].y - gm);
        v[i].z = __expf(v[i].z - gm);
        v[i].w = __expf(v[i].w - gm);
        s += v[i].x + v[i].y + v[i].z + v[i].w;
    }
#pragma unroll
    for (int off = 16; off > 0; off >>= 1)
        s += __shfl_xor_sync(0xffffffffu, s, off);
    if (lane == 0) red_sum[warp] = s;
    __syncthreads();
    float gs = 0.0f;
#pragma unroll
    for (int w = 0; w < 8; w++) gs += red_sum[w];

    const float inv = 1.0f / gs;
#pragma unroll
    for (int i = 0; i < 4; i++) {
        const int f = tid + 256 * i;
        __half2 a, b;
        a.x = __float2half_rn(v[i].x * inv); a.y = __float2half_rn(v[i].y * inv);
        b.x = __float2half_rn(v[i].z * inv); b.y = __float2half_rn(v[i].w * inv);
        ((__half2*)(ph + rowoff))[f * 2]     = a;
        ((__half2*)(ph + rowoff))[f * 2 + 1] = b;
    }
}

// ---------------------------------------------------------------------------
extern "C" void kernel_launch(void* const* d_in, const int* in_sizes, int n_in,
                              void* d_out, int out_size)
{
    const float* token = (const float*)d_in[0];
    const float* W1    = (const float*)d_in[1];
    const float* W2    = (const float*)d_in[2];
    const float* W3    = (const float*)d_in[3];
    float*       out   = (float*)d_out;

    __half *thi, *tlo, *w1h, *w2h, *w3h, *w3l;
    __half *qhi, *qlo, *kk, *vt, *pp;
    float* sc;
    cudaGetSymbolAddress((void**)&thi, g_thi);  cudaGetSymbolAddress((void**)&tlo, g_tlo);
    cudaGetSymbolAddress((void**)&w1h, g_w1h);  cudaGetSymbolAddress((void**)&w2h, g_w2h);
    cudaGetSymbolAddress((void**)&w3h, g_w3h);  cudaGetSymbolAddress((void**)&w3l, g_w3l);
    cudaGetSymbolAddress((void**)&qhi, g_qhi);  cudaGetSymbolAddress((void**)&qlo, g_qlo);
    cudaGetSymbolAddress((void**)&kk,  g_k);    cudaGetSymbolAddress((void**)&vt,  g_vt);
    cudaGetSymbolAddress((void**)&pp,  g_p);
    cudaGetSymbolAddress((void**)&sc,  g_sc);

    const int SM2 = NSTAGE * 3 * TILE_BYTES;   // NPROD=2 : 72 KB
    const int SM1 = NSTAGE * 2 * TILE_BYTES;   // NPROD=1 : 48 KB
    cudaFuncSetAttribute((const void*)mma_gemm<0, 2>, cudaFuncAttributeMaxDynamicSharedMemorySize, SM2);
    cudaFuncSetAttribute((const void*)mma_gemm<1, 2>, cudaFuncAttributeMaxDynamicSharedMemorySize, SM2);
    cudaFuncSetAttribute((const void*)mma_gemm<2, 2>, cudaFuncAttributeMaxDynamicSharedMemorySize, SM2);
    cudaFuncSetAttribute((const void*)mma_gemm<0, 1>, cudaFuncAttributeMaxDynamicSharedMemorySize, SM1);

    // 1. conversions (2 launches)
    split_kernel<<<BB * SS * DD / 4 / 256, 256>>>(token, thi, tlo, BB * SS * DD / 4);
    wconv_kernel<<<3 * DD * DD / 4 / 256, 256>>>(W1, W2, W3, w1h, w2h, w3h, w3l);

    // 2. Q = token @ W1^T  -> fp16 hi/lo
    mma_gemm<1, 2><<<dim3(DD / 128, BB * SS / 128, 1), 256, SM2>>>(
        thi, tlo, DD, 0, w1h, DD, 0, nullptr, qhi, qlo, DD, 0, DD);
    // 3. K = token @ W2^T  -> fp16 single
    mma_gemm<2, 2><<<dim3(DD / 128, BB * SS / 128, 1), 256, SM2>>>(
        thi, tlo, DD, 0, w2h, DD, 0, nullptr, kk, nullptr, DD, 0, DD);
    // 4. VT = W3 @ token^T -> fp16 single  [512, 16384]
    mma_gemm<2, 2><<<dim3(BB * SS / 128, DD / 128, 1), 256, SM2>>>(
        w3h, w3l, DD, 0, thi, DD, 0, nullptr, vt, nullptr, BB * SS, 0, DD);
    // 5. logits = Q @ K^T per batch -> fp32
    mma_gemm<0, 2><<<dim3(SS / 128, SS / 128, BB), 256, SM2>>>(
        qhi, qlo, DD, (long long)SS * DD, kk, DD, (long long)SS * DD,
        sc, nullptr, nullptr, SS, (long long)SS * SS, DD);
    // 6. softmax -> single fp16 P
    softmax_kernel<<<BB * SS, 256>>>(sc, pp);
    // 7. out = P @ VT^T per batch -> fp32 (single product)
    mma_gemm<0, 1><<<dim3(DD / 128, SS / 128, BB), 256, SM1>>>(
        pp, nullptr, SS, (long long)SS * SS, vt, BB * SS, (long long)SS,
        out, nullptr, nullptr, DD, (long long)SS * DD, SS);
}

// round 7
// speedup vs baseline: 6.6964x; 1.3319x over previous
#include <cuda_runtime.h>
#include <cuda_fp16.h>
#include <math.h>
#include <stdint.h>

#define BB 4
#define SS 4096
#define DD 512

// ---------------- scratch (static device globals) ----------------
__device__ __half g_thi[BB * SS * DD];             // token hi
__device__ __half g_tlo[BB * SS * DD];             // token lo
__device__ __half g_w1h[DD * DD];                  // W1 single
__device__ __half g_w2h[DD * DD];                  // W2 single
__device__ __half g_w3h[DD * DD];                  // W3 hi
__device__ __half g_w3l[DD * DD];                  // W3 lo
__device__ __half g_q  [BB * SS * DD];             // Q single
__device__ __half g_k  [BB * SS * DD];             // K single
__device__ __half g_vt [DD * BB * SS];             // V^T single [DD, BB*SS]
__device__ float  g_sc [(size_t)BB * SS * SS];
__device__ __half g_p  [(size_t)BB * SS * SS];     // softmax probs, single fp16

// ---------------- PTX helpers (baseline ISA, sm_80-class) ----------------
__device__ __forceinline__ uint32_t smem_u32(const void* p) {
    return (uint32_t)__cvta_generic_to_shared(p);
}
__device__ __forceinline__ void cp_async16(uint32_t s, const void* g) {
    asm volatile("cp.async.cg.shared.global [%0], [%1], 16;" :: "r"(s), "l"(g));
}
__device__ __forceinline__ void cp_commit() {
    asm volatile("cp.async.commit_group;" ::: "memory");
}
template <int N>
__device__ __forceinline__ void cp_wait() {
    asm volatile("cp.async.wait_group %0;" :: "n"(N) : "memory");
}
__device__ __forceinline__ void ldsm4(uint32_t* r, uint32_t addr) {
    asm volatile("ldmatrix.sync.aligned.m8n8.x4.shared.b16 {%0,%1,%2,%3}, [%4];"
                 : "=r"(r[0]), "=r"(r[1]), "=r"(r[2]), "=r"(r[3]) : "r"(addr));
}
__device__ __forceinline__ void mma16816(float* d, const uint32_t* a, uint32_t b0, uint32_t b1) {
    asm volatile("mma.sync.aligned.m16n8k16.row.col.f32.f16.f16.f32 "
                 "{%0,%1,%2,%3}, {%4,%5,%6,%7}, {%8,%9}, {%0,%1,%2,%3};"
                 : "+f"(d[0]), "+f"(d[1]), "+f"(d[2]), "+f"(d[3])
                 : "r"(a[0]), "r"(a[1]), "r"(a[2]), "r"(a[3]), "r"(b0), "r"(b1));
}

#define NSTAGE 3

// swizzled smem offset; row width = KCH*2 bytes, chunk = 16 B unit
template <int KCH>
__device__ __forceinline__ uint32_t swz(int row, int chunk) {
    if (KCH == 32)
        return (uint32_t)(row * 64 + (((chunk ^ ((row >> 1) & 3)) & 3) << 4));
    else
        return (uint32_t)(row * 128 + (((chunk ^ (row & 7)) & 7) << 4));
}

__device__ __forceinline__ void split2(float x, __half& h, __half& l) {
    h = __float2half_rn(x);
    l = __float2half_rn(x - __half2float(h));
}

// ---------------------------------------------------------------------------
// split-fp16 NT GEMM on HMMA: C[m,n] = sum_k A[m,k]*B[n,k]
//   NPROD=2: A = Ah + Al (fp16 pair); NPROD=1: A single fp16. B single fp16.
// OUTMODE 0: fp32 C; OUTMODE 2: fp16 single C.
// M,N multiples of 128; K multiple of KCH.
// ---------------------------------------------------------------------------
template <int OUTMODE, int NPROD, int KCH>
__global__ __launch_bounds__(256, 2)
void mma_gemm(const __half* __restrict__ Ahi, const __half* __restrict__ Alo,
              int lda, long long sA,
              const __half* __restrict__ Bs, int ldb, long long sB,
              float* __restrict__ Cf, __half* __restrict__ Ch,
              int ldc, long long sC, int K)
{
    constexpr int TILE_BYTES  = 128 * KCH * 2;
    constexpr int STAGE_BYTES = (NPROD + 1) * TILE_BYTES;
    constexpr int CPR = KCH / 8;            // 16B chunks per row
    constexpr int LITER = KCH / 16;         // loader iterations per tile

    extern __shared__ __align__(1024) char smem[];
    const int tid  = threadIdx.x;
    const int wid  = tid >> 5;
    const int lane = tid & 31;

    const long long zz = blockIdx.z;
    const __half* pAhi = Ahi + zz * sA;
    const __half* pAlo = (NPROD == 2) ? (Alo + zz * sA) : nullptr;
    const __half* pB   = Bs  + zz * sB;

    const int m0 = blockIdx.y * 128;
    const int n0 = blockIdx.x * 128;

    uint32_t s_off[LITER];
    int g_row[LITER], g_col[LITER];
#pragma unroll
    for (int i = 0; i < LITER; i++) {
        const int idx = tid + (i << 8);
        const int row = idx / CPR;
        const int c   = idx % CPR;
        s_off[i] = swz<KCH>(row, c);
        g_row[i] = row;
        g_col[i] = c * 8;
    }

    const int nkt = K / KCH;

    auto load_stage = [&](int kt) {
        const uint32_t sb32 = smem_u32(smem) + (uint32_t)((kt % NSTAGE) * STAGE_BYTES);
        const int kb = kt * KCH;
#pragma unroll
        for (int i = 0; i < LITER; i++) {
            const long long ga = (long long)(m0 + g_row[i]) * lda + kb + g_col[i];
            const long long gb = (long long)(n0 + g_row[i]) * ldb + kb + g_col[i];
            cp_async16(sb32 + s_off[i], pAhi + ga);
            if (NPROD == 2) cp_async16(sb32 + TILE_BYTES + s_off[i], pAlo + ga);
            cp_async16(sb32 + NPROD * TILE_BYTES + s_off[i], pB + gb);
        }
        cp_commit();
    };

    float acc[4][4][4];
#pragma unroll
    for (int a = 0; a < 4; a++)
#pragma unroll
        for (int b = 0; b < 4; b++)
#pragma unroll
            for (int c = 0; c < 4; c++) acc[a][b][c] = 0.0f;

    const int wm = wid >> 2;               // m offset 64*wm
    const int wn = wid & 3;                // n offset 32*wn
    const int r8 = lane & 7;
    const int aRowSel = (lane >> 3) & 1;
    const int aChkSel = (lane >> 4) & 1;
    const int bRowSel = (lane >> 4) & 1;
    const int bChkSel = (lane >> 3) & 1;

    load_stage(0);
    load_stage(1);

    for (int kt = 0; kt < nkt; kt++) {
        if (kt + 2 < nkt) load_stage(kt + 2);
        if (kt + 2 < nkt)      cp_wait<2>();
        else if (kt + 1 < nkt) cp_wait<1>();
        else                   cp_wait<0>();
        __syncthreads();

        const uint32_t aB = smem_u32(smem) + (uint32_t)((kt % NSTAGE) * STAGE_BYTES);
        const uint32_t bB = aB + NPROD * TILE_BYTES;

#pragma unroll
        for (int h = 0; h < KCH / 16; h++) {
            const int kc = 2 * h;
            uint32_t bfr[8];
#pragma unroll
            for (int p = 0; p < 2; p++) {
                const int brow = wn * 32 + p * 16 + bRowSel * 8 + r8;
                const uint32_t ad = bB + swz<KCH>(brow, kc + bChkSel);
                ldsm4(&bfr[p * 4], ad);
            }
#pragma unroll
            for (int mt = 0; mt < 4; mt++) {
                const int arow = wm * 64 + mt * 16 + aRowSel * 8 + r8;
                const uint32_t ad = aB + swz<KCH>(arow, kc + aChkSel);
                uint32_t ah[4], al[4];
                ldsm4(ah, ad);
                if (NPROD == 2) ldsm4(al, ad + TILE_BYTES);
#pragma unroll
                for (int nt = 0; nt < 4; nt++) {
                    const int p  = nt >> 1;
                    const int of = (nt & 1) * 2;
                    const uint32_t b0 = bfr[p * 4 + of], b1 = bfr[p * 4 + of + 1];
                    mma16816(acc[mt][nt], ah, b0, b1);                 // Ah*B
                    if (NPROD == 2) mma16816(acc[mt][nt], al, b0, b1); // Al*B
                }
            }
        }
        __syncthreads();
    }

    // epilogue
    const int er = (lane >> 2);
    const int ec = (lane & 3) * 2;
#pragma unroll
    for (int mt = 0; mt < 4; mt++) {
#pragma unroll
        for (int nt = 0; nt < 4; nt++) {
            const int row = m0 + wm * 64 + mt * 16 + er;
            const int col = n0 + wn * 32 + nt * 8 + ec;
            float* a = acc[mt][nt];
            const long long o0 = zz * sC + (long long)row * ldc + col;
            const long long o1 = zz * sC + (long long)(row + 8) * ldc + col;
            if (OUTMODE == 0) {
                *(float2*)(Cf + o0) = make_float2(a[0], a[1]);
                *(float2*)(Cf + o1) = make_float2(a[2], a[3]);
            } else {
                __half2 v0, v1;
                v0.x = __float2half_rn(a[0]); v0.y = __float2half_rn(a[1]);
                v1.x = __float2half_rn(a[2]); v1.y = __float2half_rn(a[3]);
                *(__half2*)(Ch + o0) = v0;
                *(__half2*)(Ch + o1) = v1;
            }
        }
    }
}

// ---------------------------------------------------------------------------
// fp32 -> fp16 hi/lo split (token)
// ---------------------------------------------------------------------------
__global__ __launch_bounds__(256)
void split_kernel(const float* __restrict__ x, __half* __restrict__ hi,
                  __half* __restrict__ lo, int n4)
{
    const int i = blockIdx.x * 256 + threadIdx.x;
    if (i >= n4) return;
    float4 v = ((const float4*)x)[i];
    __half h0, h1, h2, h3, l0, l1, l2, l3;
    split2(v.x, h0, l0); split2(v.y, h1, l1);
    split2(v.z, h2, l2); split2(v.w, h3, l3);
    __half2 a, b, c, d;
    a.x = h0; a.y = h1; b.x = h2; b.y = h3;
    c.x = l0; c.y = l1; d.x = l2; d.y = l3;
    ((__half2*)hi)[i * 2]     = a;
    ((__half2*)hi)[i * 2 + 1] = b;
    ((__half2*)lo)[i * 2]     = c;
    ((__half2*)lo)[i * 2 + 1] = d;
}

// all three weight conversions in one launch: W1,W2 -> round; W3 -> split
__global__ __launch_bounds__(256)
void wconv_kernel(const float* __restrict__ W1, const float* __restrict__ W2,
                  const float* __restrict__ W3,
                  __half* __restrict__ w1h, __half* __restrict__ w2h,
                  __half* __restrict__ w3h, __half* __restrict__ w3l)
{
    const int n4 = DD * DD / 4;
    const int gi = blockIdx.x * 256 + threadIdx.x;
    const int which = gi / n4;
    const int i = gi - which * n4;
    if (which == 0 || which == 1) {
        const float* W = (which == 0) ? W1 : W2;
        __half* out = (which == 0) ? w1h : w2h;
        float4 v = ((const float4*)W)[i];
        __half2 a, b;
        a.x = __float2half_rn(v.x); a.y = __float2half_rn(v.y);
        b.x = __float2half_rn(v.z); b.y = __float2half_rn(v.w);
        ((__half2*)out)[i * 2]     = a;
        ((__half2*)out)[i * 2 + 1] = b;
    } else {
        float4 v = ((const float4*)W3)[i];
        __half h0, h1, h2, h3, l0, l1, l2, l3;
        split2(v.x, h0, l0); split2(v.y, h1, l1);
        split2(v.z, h2, l2); split2(v.w, h3, l3);
        __half2 a, b, c, d;
        a.x = h0; a.y = h1; b.x = h2; b.y = h3;
        c.x = l0; c.y = l1; d.x = l2; d.y = l3;
        ((__half2*)w3h)[i * 2]     = a;
        ((__half2*)w3h)[i * 2 + 1] = b;
        ((__half2*)w3l)[i * 2]     = c;
        ((__half2*)w3l)[i * 2 + 1] = d;
    }
}

// ---------------------------------------------------------------------------
// Row softmax (scale folded), emits single fp16 probabilities
// ---------------------------------------------------------------------------
__global__ __launch_bounds__(256)
void softmax_kernel(const float* __restrict__ scores, __half* __restrict__ ph)
{
    const float scale = 0.04419417382415922f; // 1/sqrt(512)
    const long long rowoff = (long long)blockIdx.x * SS;
    const float* p = scores + rowoff;
    const int tid = threadIdx.x;
    const int lane = tid & 31;
    const int warp = tid >> 5;

    __shared__ float red_max[8];
    __shared__ float red_sum[8];

    float4 v[4];
    float m = -3.4e38f;
#pragma unroll
    for (int i = 0; i < 4; i++) {
        v[i] = ((const float4*)p)[tid + 256 * i];
        v[i].x *= scale; v[i].y *= scale; v[i].z *= scale; v[i].w *= scale;
        m = fmaxf(m, fmaxf(fmaxf(v[i].x, v[i].y), fmaxf(v[i].z, v[i].w)));
    }
#pragma unroll
    for (int off = 16; off > 0; off >>= 1)
        m = fmaxf(m, __shfl_xor_sync(0xffffffffu, m, off));
    if (lane == 0) red_max[warp] = m;
    __syncthreads();
    float gm = red_max[0];
#pragma unroll
    for (int w = 1; w < 8; w++) gm = fmaxf(gm, red_max[w]);

    float s = 0.0f;
#pragma unroll
    for (int i = 0; i < 4; i++) {
        v[i].x = __expf(v[i].x - gm);
        v[i].y = __expf(v[i].y - gm);
        v[i].z = __expf(v[i].z - gm);
        v[i].w = __expf(v[i].w - gm);
        s += v[i].x + v[i].y + v[i].z + v[i].w;
    }
#pragma unroll
    for (int off = 16; off > 0; off >>= 1)
        s += __shfl_xor_sync(0xffffffffu, s, off);
    if (lane == 0) red_sum[warp] = s;
    __syncthreads();
    float gs = 0.0f;
#pragma unroll
    for (int w = 0; w < 8; w++) gs += red_sum[w];

    const float inv = 1.0f / gs;
#pragma unroll
    for (int i = 0; i < 4; i++) {
        const int f = tid + 256 * i;
        __half2 a, b;
        a.x = __float2half_rn(v[i].x * inv); a.y = __float2half_rn(v[i].y * inv);
        b.x = __float2half_rn(v[i].z * inv); b.y = __float2half_rn(v[i].w * inv);
        ((__half2*)(ph + rowoff))[f * 2]     = a;
        ((__half2*)(ph + rowoff))[f * 2 + 1] = b;
    }
}

// ---------------------------------------------------------------------------
extern "C" void kernel_launch(void* const* d_in, const int* in_sizes, int n_in,
                              void* d_out, int out_size)
{
    const float* token = (const float*)d_in[0];
    const float* W1    = (const float*)d_in[1];
    const float* W2    = (const float*)d_in[2];
    const float* W3    = (const float*)d_in[3];
    float*       out   = (float*)d_out;

    __half *thi, *tlo, *w1h, *w2h, *w3h, *w3l;
    __half *qq, *kk, *vt, *pp;
    float* sc;
    cudaGetSymbolAddress((void**)&thi, g_thi);  cudaGetSymbolAddress((void**)&tlo, g_tlo);
    cudaGetSymbolAddress((void**)&w1h, g_w1h);  cudaGetSymbolAddress((void**)&w2h, g_w2h);
    cudaGetSymbolAddress((void**)&w3h, g_w3h);  cudaGetSymbolAddress((void**)&w3l, g_w3l);
    cudaGetSymbolAddress((void**)&qq,  g_q);    cudaGetSymbolAddress((void**)&kk,  g_k);
    cudaGetSymbolAddress((void**)&vt,  g_vt);   cudaGetSymbolAddress((void**)&pp,  g_p);
    cudaGetSymbolAddress((void**)&sc,  g_sc);

    const int SM_P = NSTAGE * 3 * (128 * 32 * 2);   // proj: NPROD=2, KCH=32 -> 72 KB
    const int SM_A = NSTAGE * 2 * (128 * 64 * 2);   // attn: NPROD=1, KCH=64 -> 96 KB
    cudaFuncSetAttribute((const void*)mma_gemm<2, 2, 32>, cudaFuncAttributeMaxDynamicSharedMemorySize, SM_P);
    cudaFuncSetAttribute((const void*)mma_gemm<0, 1, 64>, cudaFuncAttributeMaxDynamicSharedMemorySize, SM_A);

    // 1. conversions
    split_kernel<<<BB * SS * DD / 4 / 256, 256>>>(token, thi, tlo, BB * SS * DD / 4);
    wconv_kernel<<<3 * DD * DD / 4 / 256, 256>>>(W1, W2, W3, w1h, w2h, w3h, w3l);

    // 2. Q = token @ W1^T  -> fp16 single
    mma_gemm<2, 2, 32><<<dim3(DD / 128, BB * SS / 128, 1), 256, SM_P>>>(
        thi, tlo, DD, 0, w1h, DD, 0, nullptr, qq, DD, 0, DD);
    // 3. K = token @ W2^T  -> fp16 single
    mma_gemm<2, 2, 32><<<dim3(DD / 128, BB * SS / 128, 1), 256, SM_P>>>(
        thi, tlo, DD, 0, w2h, DD, 0, nullptr, kk, DD, 0, DD);
    // 4. VT = W3 @ token^T -> fp16 single  [512, 16384]
    mma_gemm<2, 2, 32><<<dim3(BB * SS / 128, DD / 128, 1), 256, SM_P>>>(
        w3h, w3l, DD, 0, thi, DD, 0, nullptr, vt, BB * SS, 0, DD);
    // 5. logits = Q @ K^T per batch -> fp32 (single product)
    mma_gemm<0, 1, 64><<<dim3(SS / 128, SS / 128, BB), 256, SM_A>>>(
        qq, nullptr, DD, (long long)SS * DD, kk, DD, (long long)SS * DD,
        sc, nullptr, SS, (long long)SS * SS, DD);
    // 6. softmax -> single fp16 P
    softmax_kernel<<<BB * SS, 256>>>(sc, pp);
    // 7. out = P @ VT^T per batch -> fp32 (single product)
    mma_gemm<0, 1, 64><<<dim3(DD / 128, SS / 128, BB), 256, SM_A>>>(
        pp, nullptr, SS, (long long)SS * SS, vt, BB * SS, (long long)SS,
        out, nullptr, DD, (long long)SS * DD, SS);
}

// round 8
// speedup vs baseline: 7.6250x; 1.1387x over previous
#include <cuda_runtime.h>
#include <cuda_fp16.h>
#include <math.h>
#include <stdint.h>

#define BB 4
#define SS 4096
#define DD 512

// ---------------- scratch (static device globals) ----------------
__device__ __half g_t  [BB * SS * DD];             // token fp16
__device__ __half g_w1h[DD * DD];
__device__ __half g_w2h[DD * DD];
__device__ __half g_w3h[DD * DD];
__device__ __half g_q  [BB * SS * DD];
__device__ __half g_k  [BB * SS * DD];
__device__ __half g_vt [DD * BB * SS];             // V^T [DD, BB*SS]
__device__ float  g_sc [(size_t)BB * SS * SS];
__device__ __half g_p  [(size_t)BB * SS * SS];

// ---------------- PTX helpers (baseline ISA, sm_80-class) ----------------
__device__ __forceinline__ uint32_t smem_u32(const void* p) {
    return (uint32_t)__cvta_generic_to_shared(p);
}
__device__ __forceinline__ void cp_async16(uint32_t s, const void* g) {
    asm volatile("cp.async.cg.shared.global [%0], [%1], 16;" :: "r"(s), "l"(g));
}
__device__ __forceinline__ void cp_commit() {
    asm volatile("cp.async.commit_group;" ::: "memory");
}
template <int N>
__device__ __forceinline__ void cp_wait() {
    asm volatile("cp.async.wait_group %0;" :: "n"(N) : "memory");
}
__device__ __forceinline__ void ldsm4(uint32_t* r, uint32_t addr) {
    asm volatile("ldmatrix.sync.aligned.m8n8.x4.shared.b16 {%0,%1,%2,%3}, [%4];"
                 : "=r"(r[0]), "=r"(r[1]), "=r"(r[2]), "=r"(r[3]) : "r"(addr));
}
__device__ __forceinline__ void mma16816(float* d, const uint32_t* a, uint32_t b0, uint32_t b1) {
    asm volatile("mma.sync.aligned.m16n8k16.row.col.f32.f16.f16.f32 "
                 "{%0,%1,%2,%3}, {%4,%5,%6,%7}, {%8,%9}, {%0,%1,%2,%3};"
                 : "+f"(d[0]), "+f"(d[1]), "+f"(d[2]), "+f"(d[3])
                 : "r"(a[0]), "r"(a[1]), "r"(a[2]), "r"(a[3]), "r"(b0), "r"(b1));
}

// KCH=64: row = 128 B = 8 chunks of 16 B; swizzle chunk ^ (row&7)
#define KCH 64
#define TILE_BYTES (128 * KCH * 2)          // 16 KB
#define STAGE_BYTES (2 * TILE_BYTES)        // A + B = 32 KB
#define NSTAGE 3
#define SMEM_BYTES (NSTAGE * STAGE_BYTES)   // 96 KB -> 2 CTAs/SM

__device__ __forceinline__ uint32_t swz(int row, int chunk) {
    return (uint32_t)(row * 128 + (((chunk ^ (row & 7)) & 7) << 4));
}

// ---------------------------------------------------------------------------
// single-fp16 NT GEMM on HMMA: C[m,n] = sum_k A[m,k]*B[n,k]
// OUTMODE 0: fp32 C; OUTMODE 2: fp16 C.
// M,N multiples of 128; K multiple of 64.
// ---------------------------------------------------------------------------
template <int OUTMODE>
__global__ __launch_bounds__(256, 2)
void mma_gemm(const __half* __restrict__ As, int lda, long long sA,
              const __half* __restrict__ Bs, int ldb, long long sB,
              float* __restrict__ Cf, __half* __restrict__ Ch,
              int ldc, long long sC, int K)
{
    extern __shared__ __align__(1024) char smem[];
    const int tid  = threadIdx.x;
    const int wid  = tid >> 5;
    const int lane = tid & 31;

    const long long zz = blockIdx.z;
    const __half* pA = As + zz * sA;
    const __half* pB = Bs + zz * sB;

    const int m0 = blockIdx.y * 128;
    const int n0 = blockIdx.x * 128;

    // loader: 1024 chunks of 16B per tile; 4 iters x 256 threads
    uint32_t s_off[4];
    int g_row[4], g_col[4];
#pragma unroll
    for (int i = 0; i < 4; i++) {
        const int idx = tid + (i << 8);
        const int row = idx >> 3;
        const int c   = idx & 7;
        s_off[i] = swz(row, c);
        g_row[i] = row;
        g_col[i] = c * 8;
    }

    const int nkt = K / KCH;

    auto load_stage = [&](int kt) {
        const uint32_t sb32 = smem_u32(smem) + (uint32_t)((kt % NSTAGE) * STAGE_BYTES);
        const int kb = kt * KCH;
#pragma unroll
        for (int i = 0; i < 4; i++) {
            const long long ga = (long long)(m0 + g_row[i]) * lda + kb + g_col[i];
            const long long gb = (long long)(n0 + g_row[i]) * ldb + kb + g_col[i];
            cp_async16(sb32 + s_off[i],              pA + ga);
            cp_async16(sb32 + TILE_BYTES + s_off[i], pB + gb);
        }
        cp_commit();
    };

    float acc[4][4][4];
#pragma unroll
    for (int a = 0; a < 4; a++)
#pragma unroll
        for (int b = 0; b < 4; b++)
#pragma unroll
            for (int c = 0; c < 4; c++) acc[a][b][c] = 0.0f;

    const int wm = wid >> 2;               // m offset 64*wm
    const int wn = wid & 3;                // n offset 32*wn
    const int r8 = lane & 7;
    const int aRowSel = (lane >> 3) & 1;
    const int aChkSel = (lane >> 4) & 1;
    const int bRowSel = (lane >> 4) & 1;
    const int bChkSel = (lane >> 3) & 1;

    load_stage(0);
    load_stage(1);

    for (int kt = 0; kt < nkt; kt++) {
        if (kt + 2 < nkt) load_stage(kt + 2);
        if (kt + 2 < nkt)      cp_wait<2>();
        else if (kt + 1 < nkt) cp_wait<1>();
        else                   cp_wait<0>();
        __syncthreads();

        const uint32_t aB = smem_u32(smem) + (uint32_t)((kt % NSTAGE) * STAGE_BYTES);
        const uint32_t bB = aB + TILE_BYTES;

#pragma unroll
        for (int h = 0; h < KCH / 16; h++) {
            const int kc = 2 * h;
            uint32_t bfr[8];
#pragma unroll
            for (int p = 0; p < 2; p++) {
                const int brow = wn * 32 + p * 16 + bRowSel * 8 + r8;
                const uint32_t ad = bB + swz(brow, kc + bChkSel);
                ldsm4(&bfr[p * 4], ad);
            }
#pragma unroll
            for (int mt = 0; mt < 4; mt++) {
                const int arow = wm * 64 + mt * 16 + aRowSel * 8 + r8;
                const uint32_t ad = aB + swz(arow, kc + aChkSel);
                uint32_t ah[4];
                ldsm4(ah, ad);
#pragma unroll
                for (int nt = 0; nt < 4; nt++) {
                    const int p  = nt >> 1;
                    const int of = (nt & 1) * 2;
                    mma16816(acc[mt][nt], ah, bfr[p * 4 + of], bfr[p * 4 + of + 1]);
                }
            }
        }
        __syncthreads();
    }

    // epilogue
    const int er = (lane >> 2);
    const int ec = (lane & 3) * 2;
#pragma unroll
    for (int mt = 0; mt < 4; mt++) {
#pragma unroll
        for (int nt = 0; nt < 4; nt++) {
            const int row = m0 + wm * 64 + mt * 16 + er;
            const int col = n0 + wn * 32 + nt * 8 + ec;
            float* a = acc[mt][nt];
            const long long o0 = zz * sC + (long long)row * ldc + col;
            const long long o1 = zz * sC + (long long)(row + 8) * ldc + col;
            if (OUTMODE == 0) {
                *(float2*)(Cf + o0) = make_float2(a[0], a[1]);
                *(float2*)(Cf + o1) = make_float2(a[2], a[3]);
            } else {
                __half2 v0, v1;
                v0.x = __float2half_rn(a[0]); v0.y = __float2half_rn(a[1]);
                v1.x = __float2half_rn(a[2]); v1.y = __float2half_rn(a[3]);
                *(__half2*)(Ch + o0) = v0;
                *(__half2*)(Ch + o1) = v1;
            }
        }
    }
}

// ---------------------------------------------------------------------------
// fp32 -> fp16 round (vectorized by 4)
// ---------------------------------------------------------------------------
__global__ __launch_bounds__(256)
void round_kernel(const float* __restrict__ x, __half* __restrict__ h, int n4)
{
    const int i = blockIdx.x * 256 + threadIdx.x;
    if (i >= n4) return;
    float4 v = ((const float4*)x)[i];
    __half2 a, b;
    a.x = __float2half_rn(v.x); a.y = __float2half_rn(v.y);
    b.x = __float2half_rn(v.z); b.y = __float2half_rn(v.w);
    ((__half2*)h)[i * 2]     = a;
    ((__half2*)h)[i * 2 + 1] = b;
}

// three weight rounds in one launch
__global__ __launch_bounds__(256)
void wconv_kernel(const float* __restrict__ W1, const float* __restrict__ W2,
                  const float* __restrict__ W3,
                  __half* __restrict__ w1h, __half* __restrict__ w2h,
                  __half* __restrict__ w3h)
{
    const int n4 = DD * DD / 4;
    const int gi = blockIdx.x * 256 + threadIdx.x;
    const int which = gi / n4;
    const int i = gi - which * n4;
    const float* W = (which == 0) ? W1 : (which == 1) ? W2 : W3;
    __half* out    = (which == 0) ? w1h : (which == 1) ? w2h : w3h;
    float4 v = ((const float4*)W)[i];
    __half2 a, b;
    a.x = __float2half_rn(v.x); a.y = __float2half_rn(v.y);
    b.x = __float2half_rn(v.z); b.y = __float2half_rn(v.w);
    ((__half2*)out)[i * 2]     = a;
    ((__half2*)out)[i * 2 + 1] = b;
}

// ---------------------------------------------------------------------------
// Row softmax (scale folded), emits single fp16 probabilities
// ---------------------------------------------------------------------------
__global__ __launch_bounds__(256)
void softmax_kernel(const float* __restrict__ scores, __half* __restrict__ ph)
{
    const float scale = 0.04419417382415922f; // 1/sqrt(512)
    const long long rowoff = (long long)blockIdx.x * SS;
    const float* p = scores + rowoff;
    const int tid = threadIdx.x;
    const int lane = tid & 31;
    const int warp = tid >> 5;

    __shared__ float red_max[8];
    __shared__ float red_sum[8];

    float4 v[4];
    float m = -3.4e38f;
#pragma unroll
    for (int i = 0; i < 4; i++) {
        v[i] = ((const float4*)p)[tid + 256 * i];
        v[i].x *= scale; v[i].y *= scale; v[i].z *= scale; v[i].w *= scale;
        m = fmaxf(m, fmaxf(fmaxf(v[i].x, v[i].y), fmaxf(v[i].z, v[i].w)));
    }
#pragma unroll
    for (int off = 16; off > 0; off >>= 1)
        m = fmaxf(m, __shfl_xor_sync(0xffffffffu, m, off));
    if (lane == 0) red_max[warp] = m;
    __syncthreads();
    float gm = red_max[0];
#pragma unroll
    for (int w = 1; w < 8; w++) gm = fmaxf(gm, red_max[w]);

    float s = 0.0f;
#pragma unroll
    for (int i = 0; i < 4; i++) {
        v[i].x = __expf(v[i].x - gm);
        v[i].y = __expf(v[i].y - gm);
        v[i].z = __expf(v[i].z - gm);
        v[i].w = __expf(v[i].w - gm);
        s += v[i].x + v[i].y + v[i].z + v[i].w;
    }
#pragma unroll
    for (int off = 16; off > 0; off >>= 1)
        s += __shfl_xor_sync(0xffffffffu, s, off);
    if (lane == 0) red_sum[warp] = s;
    __syncthreads();
    float gs = 0.0f;
#pragma unroll
    for (int w = 0; w < 8; w++) gs += red_sum[w];

    const float inv = 1.0f / gs;
#pragma unroll
    for (int i = 0; i < 4; i++) {
        const int f = tid + 256 * i;
        __half2 a, b;
        a.x = __float2half_rn(v[i].x * inv); a.y = __float2half_rn(v[i].y * inv);
        b.x = __float2half_rn(v[i].z * inv); b.y = __float2half_rn(v[i].w * inv);
        ((__half2*)(ph + rowoff))[f * 2]     = a;
        ((__half2*)(ph + rowoff))[f * 2 + 1] = b;
    }
}

// ---------------------------------------------------------------------------
extern "C" void kernel_launch(void* const* d_in, const int* in_sizes, int n_in,
                              void* d_out, int out_size)
{
    const float* token = (const float*)d_in[0];
    const float* W1    = (const float*)d_in[1];
    const float* W2    = (const float*)d_in[2];
    const float* W3    = (const float*)d_in[3];
    float*       out   = (float*)d_out;

    __half *th, *w1h, *w2h, *w3h, *qq, *kk, *vt, *pp;
    float* sc;
    cudaGetSymbolAddress((void**)&th,  g_t);
    cudaGetSymbolAddress((void**)&w1h, g_w1h);  cudaGetSymbolAddress((void**)&w2h, g_w2h);
    cudaGetSymbolAddress((void**)&w3h, g_w3h);
    cudaGetSymbolAddress((void**)&qq,  g_q);    cudaGetSymbolAddress((void**)&kk,  g_k);
    cudaGetSymbolAddress((void**)&vt,  g_vt);   cudaGetSymbolAddress((void**)&pp,  g_p);
    cudaGetSymbolAddress((void**)&sc,  g_sc);

    cudaFuncSetAttribute((const void*)mma_gemm<0>, cudaFuncAttributeMaxDynamicSharedMemorySize, SMEM_BYTES);
    cudaFuncSetAttribute((const void*)mma_gemm<2>, cudaFuncAttributeMaxDynamicSharedMemorySize, SMEM_BYTES);

    // 1. conversions
    round_kernel<<<BB * SS * DD / 4 / 256, 256>>>(token, th, BB * SS * DD / 4);
    wconv_kernel<<<3 * DD * DD / 4 / 256, 256>>>(W1, W2, W3, w1h, w2h, w3h);

    // 2. Q = token @ W1^T  -> fp16
    mma_gemm<2><<<dim3(DD / 128, BB * SS / 128, 1), 256, SMEM_BYTES>>>(
        th, DD, 0, w1h, DD, 0, nullptr, qq, DD, 0, DD);
    // 3. K = token @ W2^T  -> fp16
    mma_gemm<2><<<dim3(DD / 128, BB * SS / 128, 1), 256, SMEM_BYTES>>>(
        th, DD, 0, w2h, DD, 0, nullptr, kk, DD, 0, DD);
    // 4. VT = W3 @ token^T -> fp16  [512, 16384]
    mma_gemm<2><<<dim3(BB * SS / 128, DD / 128, 1), 256, SMEM_BYTES>>>(
        w3h, DD, 0, th, DD, 0, nullptr, vt, BB * SS, 0, DD);
    // 5. logits = Q @ K^T per batch -> fp32
    mma_gemm<0><<<dim3(SS / 128, SS / 128, BB), 256, SMEM_BYTES>>>(
        qq, DD, (long long)SS * DD, kk, DD, (long long)SS * DD,
        sc, nullptr, SS, (long long)SS * SS, DD);
    // 6. softmax -> fp16 P
    softmax_kernel<<<BB * SS, 256>>>(sc, pp);
    // 7. out = P @ VT^T per batch -> fp32
    mma_gemm<0><<<dim3(DD / 128, SS / 128, BB), 256, SMEM_BYTES>>>(
        pp, SS, (long long)SS * SS, vt, BB * SS, (long long)SS,
        out, nullptr, DD, (long long)SS * DD, SS);
}

// round 9
// speedup vs baseline: 7.7494x; 1.0163x over previous
#include <cuda_runtime.h>
#include <cuda_fp16.h>
#include <math.h>
#include <stdint.h>

#define BB 4
#define SS 4096
#define DD 512

// ---------------- scratch (static device globals) ----------------
__device__ __half g_t   [BB * SS * DD];            // token fp16
__device__ __half g_w12h[2 * DD * DD];             // [W1; W2] rows 0..1023
__device__ __half g_w3h [DD * DD];
__device__ __half g_qk  [BB * SS * 2 * DD];        // [16384, 1024]: Q | K
__device__ __half g_vt  [DD * BB * SS];            // V^T [DD, BB*SS]
__device__ float  g_sc  [(size_t)BB * SS * SS];
__device__ __half g_p   [(size_t)BB * SS * SS];

// ---------------- PTX helpers (baseline ISA, sm_80-class) ----------------
__device__ __forceinline__ uint32_t smem_u32(const void* p) {
    return (uint32_t)__cvta_generic_to_shared(p);
}
__device__ __forceinline__ void cp_async16(uint32_t s, const void* g) {
    asm volatile("cp.async.cg.shared.global [%0], [%1], 16;" :: "r"(s), "l"(g));
}
__device__ __forceinline__ void cp_commit() {
    asm volatile("cp.async.commit_group;" ::: "memory");
}
template <int N>
__device__ __forceinline__ void cp_wait() {
    asm volatile("cp.async.wait_group %0;" :: "n"(N) : "memory");
}
__device__ __forceinline__ void ldsm4(uint32_t* r, uint32_t addr) {
    asm volatile("ldmatrix.sync.aligned.m8n8.x4.shared.b16 {%0,%1,%2,%3}, [%4];"
                 : "=r"(r[0]), "=r"(r[1]), "=r"(r[2]), "=r"(r[3]) : "r"(addr));
}
__device__ __forceinline__ void mma16816(float* d, const uint32_t* a, uint32_t b0, uint32_t b1) {
    asm volatile("mma.sync.aligned.m16n8k16.row.col.f32.f16.f16.f32 "
                 "{%0,%1,%2,%3}, {%4,%5,%6,%7}, {%8,%9}, {%0,%1,%2,%3};"
                 : "+f"(d[0]), "+f"(d[1]), "+f"(d[2]), "+f"(d[3])
                 : "r"(a[0]), "r"(a[1]), "r"(a[2]), "r"(a[3]), "r"(b0), "r"(b1));
}

// KCH=64: row = 128 B = 8 chunks of 16 B; swizzle chunk ^ (row&7)
#define KCH 64
#define TILE_BYTES (128 * KCH * 2)          // 16 KB
#define STAGE_BYTES (2 * TILE_BYTES)        // A + B = 32 KB
#define NSTAGE 3
#define SMEM_BYTES (NSTAGE * STAGE_BYTES)   // 96 KB -> 2 CTAs/SM

__device__ __forceinline__ uint32_t swz(int row, int chunk) {
    return (uint32_t)(row * 128 + (((chunk ^ (row & 7)) & 7) << 4));
}

// ---------------------------------------------------------------------------
// single-fp16 NT GEMM on HMMA: C[m,n] = sum_k A[m,k]*B[n,k]
// OUTMODE 0: fp32 C; OUTMODE 2: fp16 C.
// M,N multiples of 128; K multiple of 64.
// ---------------------------------------------------------------------------
template <int OUTMODE>
__global__ __launch_bounds__(256, 2)
void mma_gemm(const __half* __restrict__ As, int lda, long long sA,
              const __half* __restrict__ Bs, int ldb, long long sB,
              float* __restrict__ Cf, __half* __restrict__ Ch,
              int ldc, long long sC, int K)
{
    extern __shared__ __align__(1024) char smem[];
    const int tid  = threadIdx.x;
    const int wid  = tid >> 5;
    const int lane = tid & 31;

    const long long zz = blockIdx.z;
    const __half* pA = As + zz * sA;
    const __half* pB = Bs + zz * sB;

    const int m0 = blockIdx.y * 128;
    const int n0 = blockIdx.x * 128;

    // loader: 1024 chunks of 16B per tile; 4 iters x 256 threads
    uint32_t s_off[4];
    int g_row[4], g_col[4];
#pragma unroll
    for (int i = 0; i < 4; i++) {
        const int idx = tid + (i << 8);
        const int row = idx >> 3;
        const int c   = idx & 7;
        s_off[i] = swz(row, c);
        g_row[i] = row;
        g_col[i] = c * 8;
    }

    const int nkt = K / KCH;

    auto load_stage = [&](int kt) {
        const uint32_t sb32 = smem_u32(smem) + (uint32_t)((kt % NSTAGE) * STAGE_BYTES);
        const int kb = kt * KCH;
#pragma unroll
        for (int i = 0; i < 4; i++) {
            const long long ga = (long long)(m0 + g_row[i]) * lda + kb + g_col[i];
            const long long gb = (long long)(n0 + g_row[i]) * ldb + kb + g_col[i];
            cp_async16(sb32 + s_off[i],              pA + ga);
            cp_async16(sb32 + TILE_BYTES + s_off[i], pB + gb);
        }
        cp_commit();
    };

    float acc[4][4][4];
#pragma unroll
    for (int a = 0; a < 4; a++)
#pragma unroll
        for (int b = 0; b < 4; b++)
#pragma unroll
            for (int c = 0; c < 4; c++) acc[a][b][c] = 0.0f;

    const int wm = wid >> 2;               // m offset 64*wm
    const int wn = wid & 3;                // n offset 32*wn
    const int r8 = lane & 7;
    const int aRowSel = (lane >> 3) & 1;
    const int aChkSel = (lane >> 4) & 1;
    const int bRowSel = (lane >> 4) & 1;
    const int bChkSel = (lane >> 3) & 1;

    load_stage(0);
    load_stage(1);

    for (int kt = 0; kt < nkt; kt++) {
        // stage kt complete; one newer group (kt+1) may stay in flight
        if (kt + 1 < nkt) cp_wait<1>();
        else              cp_wait<0>();
        __syncthreads();   // also proves all warps finished compute(kt-1)
        if (kt + 2 < nkt) load_stage(kt + 2);   // slot (kt+2)%3 == (kt-1)%3, now free

        const uint32_t aB = smem_u32(smem) + (uint32_t)((kt % NSTAGE) * STAGE_BYTES);
        const uint32_t bB = aB + TILE_BYTES;

#pragma unroll
        for (int h = 0; h < KCH / 16; h++) {
            const int kc = 2 * h;
            uint32_t bfr[8];
#pragma unroll
            for (int p = 0; p < 2; p++) {
                const int brow = wn * 32 + p * 16 + bRowSel * 8 + r8;
                const uint32_t ad = bB + swz(brow, kc + bChkSel);
                ldsm4(&bfr[p * 4], ad);
            }
#pragma unroll
            for (int mt = 0; mt < 4; mt++) {
                const int arow = wm * 64 + mt * 16 + aRowSel * 8 + r8;
                const uint32_t ad = aB + swz(arow, kc + aChkSel);
                uint32_t ah[4];
                ldsm4(ah, ad);
#pragma unroll
                for (int nt = 0; nt < 4; nt++) {
                    const int p  = nt >> 1;
                    const int of = (nt & 1) * 2;
                    mma16816(acc[mt][nt], ah, bfr[p * 4 + of], bfr[p * 4 + of + 1]);
                }
            }
        }
    }

    // epilogue
    const int er = (lane >> 2);
    const int ec = (lane & 3) * 2;
#pragma unroll
    for (int mt = 0; mt < 4; mt++) {
#pragma unroll
        for (int nt = 0; nt < 4; nt++) {
            const int row = m0 + wm * 64 + mt * 16 + er;
            const int col = n0 + wn * 32 + nt * 8 + ec;
            float* a = acc[mt][nt];
            const long long o0 = zz * sC + (long long)row * ldc + col;
            const long long o1 = zz * sC + (long long)(row + 8) * ldc + col;
            if (OUTMODE == 0) {
                *(float2*)(Cf + o0) = make_float2(a[0], a[1]);
                *(float2*)(Cf + o1) = make_float2(a[2], a[3]);
            } else {
                __half2 v0, v1;
                v0.x = __float2half_rn(a[0]); v0.y = __float2half_rn(a[1]);
                v1.x = __float2half_rn(a[2]); v1.y = __float2half_rn(a[3]);
                *(__half2*)(Ch + o0) = v0;
                *(__half2*)(Ch + o1) = v1;
            }
        }
    }
}

// ---------------------------------------------------------------------------
// fp32 -> fp16 round (vectorized by 4)
// ---------------------------------------------------------------------------
__global__ __launch_bounds__(256)
void round_kernel(const float* __restrict__ x, __half* __restrict__ h, int n4)
{
    const int i = blockIdx.x * 256 + threadIdx.x;
    if (i >= n4) return;
    float4 v = ((const float4*)x)[i];
    __half2 a, b;
    a.x = __float2half_rn(v.x); a.y = __float2half_rn(v.y);
    b.x = __float2half_rn(v.z); b.y = __float2half_rn(v.w);
    ((__half2*)h)[i * 2]     = a;
    ((__half2*)h)[i * 2 + 1] = b;
}

// three weight rounds in one launch: W1 -> w12h rows 0..511, W2 -> rows 512..1023, W3 -> w3h
__global__ __launch_bounds__(256)
void wconv_kernel(const float* __restrict__ W1, const float* __restrict__ W2,
                  const float* __restrict__ W3,
                  __half* __restrict__ w12h, __half* __restrict__ w3h)
{
    const int n4 = DD * DD / 4;
    const int gi = blockIdx.x * 256 + threadIdx.x;
    const int which = gi / n4;
    const int i = gi - which * n4;
    const float* W = (which == 0) ? W1 : (which == 1) ? W2 : W3;
    __half* out    = (which == 0) ? w12h : (which == 1) ? (w12h + DD * DD) : w3h;
    float4 v = ((const float4*)W)[i];
    __half2 a, b;
    a.x = __float2half_rn(v.x); a.y = __float2half_rn(v.y);
    b.x = __float2half_rn(v.z); b.y = __float2half_rn(v.w);
    ((__half2*)out)[i * 2]     = a;
    ((__half2*)out)[i * 2 + 1] = b;
}

// ---------------------------------------------------------------------------
// Row softmax (scale folded), emits single fp16 probabilities
// ---------------------------------------------------------------------------
__global__ __launch_bounds__(256)
void softmax_kernel(const float* __restrict__ scores, __half* __restrict__ ph)
{
    const float scale = 0.04419417382415922f; // 1/sqrt(512)
    const long long rowoff = (long long)blockIdx.x * SS;
    const float* p = scores + rowoff;
    const int tid = threadIdx.x;
    const int lane = tid & 31;
    const int warp = tid >> 5;

    __shared__ float red_max[8];
    __shared__ float red_sum[8];

    float4 v[4];
    float m = -3.4e38f;
#pragma unroll
    for (int i = 0; i < 4; i++) {
        v[i] = ((const float4*)p)[tid + 256 * i];
        v[i].x *= scale; v[i].y *= scale; v[i].z *= scale; v[i].w *= scale;
        m = fmaxf(m, fmaxf(fmaxf(v[i].x, v[i].y), fmaxf(v[i].z, v[i].w)));
    }
#pragma unroll
    for (int off = 16; off > 0; off >>= 1)
        m = fmaxf(m, __shfl_xor_sync(0xffffffffu, m, off));
    if (lane == 0) red_max[warp] = m;
    __syncthreads();
    float gm = red_max[0];
#pragma unroll
    for (int w = 1; w < 8; w++) gm = fmaxf(gm, red_max[w]);

    float s = 0.0f;
#pragma unroll
    for (int i = 0; i < 4; i++) {
        v[i].x = __expf(v[i].x - gm);
        v[i].y = __expf(v[i].y - gm);
        v[i].z = __expf(v[i].z - gm);
        v[i].w = __expf(v[i].w - gm);
        s += v[i].x + v[i].y + v[i].z + v[i].w;
    }
#pragma unroll
    for (int off = 16; off > 0; off >>= 1)
        s += __shfl_xor_sync(0xffffffffu, s, off);
    if (lane == 0) red_sum[warp] = s;
    __syncthreads();
    float gs = 0.0f;
#pragma unroll
    for (int w = 0; w < 8; w++) gs += red_sum[w];

    const float inv = 1.0f / gs;
#pragma unroll
    for (int i = 0; i < 4; i++) {
        const int f = tid + 256 * i;
        __half2 a, b;
        a.x = __float2half_rn(v[i].x * inv); a.y = __float2half_rn(v[i].y * inv);
        b.x = __float2half_rn(v[i].z * inv); b.y = __float2half_rn(v[i].w * inv);
        ((__half2*)(ph + rowoff))[f * 2]     = a;
        ((__half2*)(ph + rowoff))[f * 2 + 1] = b;
    }
}

// ---------------------------------------------------------------------------
extern "C" void kernel_launch(void* const* d_in, const int* in_sizes, int n_in,
                              void* d_out, int out_size)
{
    const float* token = (const float*)d_in[0];
    const float* W1    = (const float*)d_in[1];
    const float* W2    = (const float*)d_in[2];
    const float* W3    = (const float*)d_in[3];
    float*       out   = (float*)d_out;

    __half *th, *w12h, *w3h, *qk, *vt, *pp;
    float* sc;
    cudaGetSymbolAddress((void**)&th,   g_t);
    cudaGetSymbolAddress((void**)&w12h, g_w12h);
    cudaGetSymbolAddress((void**)&w3h,  g_w3h);
    cudaGetSymbolAddress((void**)&qk,   g_qk);
    cudaGetSymbolAddress((void**)&vt,   g_vt);
    cudaGetSymbolAddress((void**)&pp,   g_p);
    cudaGetSymbolAddress((void**)&sc,   g_sc);

    cudaFuncSetAttribute((const void*)mma_gemm<0>, cudaFuncAttributeMaxDynamicSharedMemorySize, SMEM_BYTES);
    cudaFuncSetAttribute((const void*)mma_gemm<2>, cudaFuncAttributeMaxDynamicSharedMemorySize, SMEM_BYTES);

    // 1. conversions
    round_kernel<<<BB * SS * DD / 4 / 256, 256>>>(token, th, BB * SS * DD / 4);
    wconv_kernel<<<3 * DD * DD / 4 / 256, 256>>>(W1, W2, W3, w12h, w3h);

    // 2. [Q|K] = token @ [W1;W2]^T -> fp16, [16384, 1024]
    mma_gemm<2><<<dim3(2 * DD / 128, BB * SS / 128, 1), 256, SMEM_BYTES>>>(
        th, DD, 0, w12h, DD, 0, nullptr, qk, 2 * DD, 0, DD);
    // 3. VT = W3 @ token^T -> fp16  [512, 16384]
    mma_gemm<2><<<dim3(BB * SS / 128, DD / 128, 1), 256, SMEM_BYTES>>>(
        w3h, DD, 0, th, DD, 0, nullptr, vt, BB * SS, 0, DD);
    // 4. logits = Q @ K^T per batch -> fp32   (Q = qk cols 0..511, K = qk cols 512..1023)
    mma_gemm<0><<<dim3(SS / 128, SS / 128, BB), 256, SMEM_BYTES>>>(
        qk, 2 * DD, (long long)SS * 2 * DD, qk + DD, 2 * DD, (long long)SS * 2 * DD,
        sc, nullptr, SS, (long long)SS * SS, DD);
    // 5. softmax -> fp16 P
    softmax_kernel<<<BB * SS, 256>>>(sc, pp);
    // 6. out = P @ VT^T per batch -> fp32
    mma_gemm<0><<<dim3(DD / 128, SS / 128, BB), 256, SMEM_BYTES>>>(
        pp, SS, (long long)SS * SS, vt, BB * SS, (long long)SS,
        out, nullptr, DD, (long long)SS * DD, SS);
}